// round 1
// baseline (speedup 1.0000x reference)
#include <cuda_runtime.h>

// ---------------------------------------------------------------------------
// Attention_71485435675049: x[4,2048,1024] -> qkv -> MHA(16 heads, d=64) -> proj
// Round 1: fp32 baseline. Stage 1/3: 128x128x8 SGEMM. Stage 2: flash-attn,
// one query row per thread, K/V tiles in smem.
// ---------------------------------------------------------------------------

#define ATT_SCALE 0.125f   // 64^-0.5

// Scratch (allocation-free rule: __device__ globals)
__device__ float g_qkv[8192 * 3072];   // 96 MB
__device__ float g_att[8192 * 1024];   // 32 MB

// ------------------------- SGEMM ------------------------------------------
// C[M,N] = A[M,K] @ B[K,N]; MODE 0: scale cols < 1024 by ATT_SCALE (q part)
// MODE 1: add bias[col]. M%128==0, N%128==0, K%8==0 assumed.
constexpr int BM = 128, BN = 128, BK = 8, TM = 8, TN = 8;

template <int MODE>
__global__ __launch_bounds__(256) void gemm_kernel(
    const float* __restrict__ A, const float* __restrict__ B,
    const float* __restrict__ bias, float* __restrict__ C,
    int M, int N, int K)
{
    __shared__ float As[BK][BM];
    __shared__ float Bs[BK][BN];

    const int tid = threadIdx.x;
    const int tr = tid >> 4;          // 0..15
    const int tc = tid & 15;          // 0..15
    const int aRow = tid >> 1;        // 0..127
    const int aCol = (tid & 1) * 4;   // 0 or 4
    const int bRow = tid >> 5;        // 0..7
    const int bCol = (tid & 31) * 4;  // 0..124

    const float* Ab = A + (size_t)blockIdx.y * BM * K;
    const float* Bb = B + (size_t)blockIdx.x * BN;

    float acc[TM][TN] = {};

    for (int k0 = 0; k0 < K; k0 += BK) {
        float4 a4 = *(const float4*)(Ab + (size_t)aRow * K + k0 + aCol);
        As[aCol + 0][aRow] = a4.x;
        As[aCol + 1][aRow] = a4.y;
        As[aCol + 2][aRow] = a4.z;
        As[aCol + 3][aRow] = a4.w;
        *(float4*)&Bs[bRow][bCol] =
            *(const float4*)(Bb + (size_t)(k0 + bRow) * N + bCol);
        __syncthreads();

        #pragma unroll
        for (int kk = 0; kk < BK; ++kk) {
            float ar[TM], br[TN];
            *(float4*)&ar[0] = *(const float4*)&As[kk][tr * TM];
            *(float4*)&ar[4] = *(const float4*)&As[kk][tr * TM + 4];
            *(float4*)&br[0] = *(const float4*)&Bs[kk][tc * TN];
            *(float4*)&br[4] = *(const float4*)&Bs[kk][tc * TN + 4];
            #pragma unroll
            for (int i = 0; i < TM; i++)
                #pragma unroll
                for (int j = 0; j < TN; j++)
                    acc[i][j] = fmaf(ar[i], br[j], acc[i][j]);
        }
        __syncthreads();
    }

    #pragma unroll
    for (int i = 0; i < TM; i++) {
        const int row = blockIdx.y * BM + tr * TM + i;
        #pragma unroll
        for (int j = 0; j < TN; j += 4) {
            const int col = blockIdx.x * BN + tc * TN + j;
            float4 v = make_float4(acc[i][j], acc[i][j + 1],
                                   acc[i][j + 2], acc[i][j + 3]);
            if (MODE == 0) {
                if (col + 3 < 1024) {
                    v.x *= ATT_SCALE; v.y *= ATT_SCALE;
                    v.z *= ATT_SCALE; v.w *= ATT_SCALE;
                }
            } else {
                const float4 b4 = *(const float4*)(bias + col);
                v.x += b4.x; v.y += b4.y; v.z += b4.z; v.w += b4.w;
            }
            *(float4*)(C + (size_t)row * N + col) = v;
        }
    }
}

// ------------------------- Flash attention ---------------------------------
// grid: (N/64, B*H). block: 64 threads, thread t owns query row i0+t.
// qkv layout: row (b*2048+n), cols [0,1024)=q (pre-scaled), [1024,2048)=k,
// [2048,3072)=v; head h at col offset h*64.
__global__ __launch_bounds__(64) void attn_kernel(
    const float* __restrict__ qkv, float* __restrict__ out)
{
    const int bh = blockIdx.y;
    const int b = bh >> 4, h = bh & 15;
    const int t = threadIdx.x;
    const int i = blockIdx.x * 64 + t;

    const float* base = qkv + (size_t)b * 2048 * 3072;
    const int qoff = h * 64;
    const int koff = 1024 + h * 64;
    const int voff = 2048 + h * 64;

    __shared__ float Ks[64][68];   // +4 pad: 4-way instead of 32-way STS conflicts
    __shared__ float Vs[64][68];

    float q[64], o[64];
    {
        const float4* qrow = (const float4*)(base + (size_t)i * 3072 + qoff);
        #pragma unroll
        for (int d4 = 0; d4 < 16; d4++) {
            float4 v = qrow[d4];
            q[d4 * 4 + 0] = v.x; q[d4 * 4 + 1] = v.y;
            q[d4 * 4 + 2] = v.z; q[d4 * 4 + 3] = v.w;
        }
    }
    #pragma unroll
    for (int d = 0; d < 64; d++) o[d] = 0.f;

    float m = -1e30f, l = 0.f;

    for (int j0 = 0; j0 < 2048; j0 += 64) {
        __syncthreads();   // previous tile's compute done
        {
            const float4* krow = (const float4*)(base + (size_t)(j0 + t) * 3072 + koff);
            const float4* vrow = (const float4*)(base + (size_t)(j0 + t) * 3072 + voff);
            #pragma unroll
            for (int d4 = 0; d4 < 16; d4++) {
                *(float4*)&Ks[t][d4 * 4] = krow[d4];
                *(float4*)&Vs[t][d4 * 4] = vrow[d4];
            }
        }
        __syncthreads();

        #pragma unroll 1
        for (int c = 0; c < 2; c++) {   // 32-key chunks to bound registers
            float s[32];
            float cmax = -1e30f;
            #pragma unroll
            for (int jj = 0; jj < 32; jj++) {
                const int j = c * 32 + jj;
                float a0 = 0.f, a1 = 0.f, a2 = 0.f, a3 = 0.f;
                #pragma unroll
                for (int d4 = 0; d4 < 16; d4++) {
                    const float4 kv = *(const float4*)&Ks[j][d4 * 4];
                    a0 = fmaf(q[d4 * 4 + 0], kv.x, a0);
                    a1 = fmaf(q[d4 * 4 + 1], kv.y, a1);
                    a2 = fmaf(q[d4 * 4 + 2], kv.z, a2);
                    a3 = fmaf(q[d4 * 4 + 3], kv.w, a3);
                }
                s[jj] = (a0 + a1) + (a2 + a3);
                cmax = fmaxf(cmax, s[jj]);
            }
            const float mnew = fmaxf(m, cmax);
            const float corr = __expf(m - mnew);
            l *= corr;
            #pragma unroll
            for (int d = 0; d < 64; d++) o[d] *= corr;
            m = mnew;
            #pragma unroll
            for (int jj = 0; jj < 32; jj++) {
                const int j = c * 32 + jj;
                const float p = __expf(s[jj] - m);
                l += p;
                #pragma unroll
                for (int d4 = 0; d4 < 16; d4++) {
                    const float4 vv = *(const float4*)&Vs[j][d4 * 4];
                    o[d4 * 4 + 0] = fmaf(p, vv.x, o[d4 * 4 + 0]);
                    o[d4 * 4 + 1] = fmaf(p, vv.y, o[d4 * 4 + 1]);
                    o[d4 * 4 + 2] = fmaf(p, vv.z, o[d4 * 4 + 2]);
                    o[d4 * 4 + 3] = fmaf(p, vv.w, o[d4 * 4 + 3]);
                }
            }
        }
    }

    const float inv = 1.f / l;
    float* orow = out + (size_t)(b * 2048 + i) * 1024 + h * 64;
    #pragma unroll
    for (int d4 = 0; d4 < 16; d4++) {
        float4 v = make_float4(o[d4 * 4 + 0] * inv, o[d4 * 4 + 1] * inv,
                               o[d4 * 4 + 2] * inv, o[d4 * 4 + 3] * inv);
        *(float4*)&orow[d4 * 4] = v;
    }
}

// ------------------------- Launch ------------------------------------------
extern "C" void kernel_launch(void* const* d_in, const int* in_sizes, int n_in,
                              void* d_out, int out_size)
{
    const float* x     = (const float*)d_in[0];   // [4,2048,1024]
    const float* w_qkv = (const float*)d_in[1];   // [1024,3072]
    const float* w_out = (const float*)d_in[2];   // [1024,1024]
    const float* b_out = (const float*)d_in[3];   // [1024]
    float* out = (float*)d_out;                   // [4,2048,1024]

    float* qkv_ptr = nullptr;
    float* att_ptr = nullptr;
    cudaGetSymbolAddress((void**)&qkv_ptr, g_qkv);
    cudaGetSymbolAddress((void**)&att_ptr, g_att);

    // Stage 1: qkv = x @ w_qkv (q columns pre-scaled)
    gemm_kernel<0><<<dim3(3072 / BN, 8192 / BM), 256>>>(
        x, w_qkv, nullptr, qkv_ptr, 8192, 3072, 1024);

    // Stage 2: attention per (b,h), writes 'b n (h d)' layout directly
    attn_kernel<<<dim3(2048 / 64, 64), 64>>>(qkv_ptr, att_ptr);

    // Stage 3: out = att @ w_out + b_out
    gemm_kernel<1><<<dim3(1024 / BN, 8192 / BM), 256>>>(
        att_ptr, w_out, b_out, out, 8192, 1024, 1024);
}

// round 4
// speedup vs baseline: 1.2483x; 1.2483x over previous
#include <cuda_runtime.h>
#include <cuda_bf16.h>
#include <cstdint>

// ---------------------------------------------------------------------------
// Attention_71485435675049 — Round 4 (resubmit of R3; infra failure, no data)
// Stage 1/3 GEMMs on mma.sync m16n8k16 bf16 (hi/lo split, fp32 accum).
// (tcgen05 rejected: harness ptxas targets plain sm_100, no 'a' features.)
// Stage 2 attention: fp32 flash (unchanged; HMMA next round).
// ---------------------------------------------------------------------------

#define ATT_SCALE 0.125f

// ------------------------- scratch (no allocs allowed) ----------------------
__device__ float g_qkv[8192 * 3072];
__device__ float g_att[8192 * 1024];
__device__ __nv_bfloat16 g_xhi[8192 * 1024];
__device__ __nv_bfloat16 g_xlo[8192 * 1024];
__device__ __nv_bfloat16 g_wqkvt_hi[3072 * 1024];   // [N,K] transposed
__device__ __nv_bfloat16 g_wqkvt_lo[3072 * 1024];
__device__ __nv_bfloat16 g_woutt_hi[1024 * 1024];
__device__ __nv_bfloat16 g_woutt_lo[1024 * 1024];
__device__ __nv_bfloat16 g_atthi[8192 * 1024];
__device__ __nv_bfloat16 g_attlo[8192 * 1024];

// ------------------------- PTX helpers -------------------------------------
__device__ __forceinline__ uint32_t smem_u32(const void* p) {
    uint32_t a;
    asm("{ .reg .u64 t; cvta.to.shared.u64 t, %1; cvt.u32.u64 %0, t; }"
        : "=r"(a) : "l"(p));
    return a;
}

__device__ __forceinline__ void cp_async16(uint32_t dst, const void* src) {
    asm volatile("cp.async.cg.shared.global [%0], [%1], 16;\n"
                 :: "r"(dst), "l"(src));
}
#define CP_COMMIT() asm volatile("cp.async.commit_group;\n" ::: "memory")
#define CP_WAIT(n)  asm volatile("cp.async.wait_group %0;\n" :: "n"(n) : "memory")

__device__ __forceinline__ void ldm_x4(uint32_t r[4], uint32_t addr) {
    asm volatile("ldmatrix.sync.aligned.m8n8.x4.shared.b16 {%0,%1,%2,%3}, [%4];"
                 : "=r"(r[0]), "=r"(r[1]), "=r"(r[2]), "=r"(r[3]) : "r"(addr));
}

__device__ __forceinline__ void mma16816(float c[4], const uint32_t a[4],
                                         const uint32_t b[2]) {
    asm volatile(
        "mma.sync.aligned.m16n8k16.row.col.f32.bf16.bf16.f32 "
        "{%0,%1,%2,%3}, {%4,%5,%6,%7}, {%8,%9}, {%0,%1,%2,%3};"
        : "+f"(c[0]), "+f"(c[1]), "+f"(c[2]), "+f"(c[3])
        : "r"(a[0]), "r"(a[1]), "r"(a[2]), "r"(a[3]), "r"(b[0]), "r"(b[1]));
}

// ------------------------- conversion kernels ------------------------------
__global__ void split_fp32(const float* __restrict__ src,
                           __nv_bfloat16* __restrict__ hi,
                           __nv_bfloat16* __restrict__ lo, int n4) {
    int i = blockIdx.x * blockDim.x + threadIdx.x;
    if (i >= n4) return;
    float4 v = ((const float4*)src)[i];
    __nv_bfloat16 h0 = __float2bfloat16(v.x), h1 = __float2bfloat16(v.y);
    __nv_bfloat16 h2 = __float2bfloat16(v.z), h3 = __float2bfloat16(v.w);
    hi[i * 4 + 0] = h0; hi[i * 4 + 1] = h1; hi[i * 4 + 2] = h2; hi[i * 4 + 3] = h3;
    lo[i * 4 + 0] = __float2bfloat16(v.x - __bfloat162float(h0));
    lo[i * 4 + 1] = __float2bfloat16(v.y - __bfloat162float(h1));
    lo[i * 4 + 2] = __float2bfloat16(v.z - __bfloat162float(h2));
    lo[i * 4 + 3] = __float2bfloat16(v.w - __bfloat162float(h3));
}

// src[K,N] fp32 -> out[N,K] bf16 hi/lo; cols < scale_cols scaled by ATT_SCALE
__global__ void transpose_split(const float* __restrict__ src,
                                __nv_bfloat16* __restrict__ hi,
                                __nv_bfloat16* __restrict__ lo,
                                int K, int N, int scale_cols) {
    __shared__ float tile[32][33];
    const int n0 = blockIdx.x * 32, k0 = blockIdx.y * 32;
    const int tx = threadIdx.x, ty = threadIdx.y;
    #pragma unroll
    for (int j = 0; j < 4; j++) {
        int r = ty + j * 8;
        float v = src[(size_t)(k0 + r) * N + n0 + tx];
        if (n0 + tx < scale_cols) v *= ATT_SCALE;
        tile[r][tx] = v;
    }
    __syncthreads();
    #pragma unroll
    for (int j = 0; j < 4; j++) {
        int b = ty + j * 8;
        float v = tile[tx][b];
        __nv_bfloat16 h = __float2bfloat16(v);
        size_t o = (size_t)(n0 + b) * K + k0 + tx;
        hi[o] = h;
        lo[o] = __float2bfloat16(v - __bfloat162float(h));
    }
}

// ------------------------- HMMA GEMM ---------------------------------------
// C[M,N] = (Ahi+Alo)[M,K] @ (Bhi+Blo)[N,K]^T, 3-term split, fp32 accum.
// Tile 128x128, BK=32, 256 threads (warps 4x2 -> 32x64 warp tiles).
// Smem rows padded to 40 bf16 (80B): conflict-free ldmatrix + STS.
constexpr int ROWB = 80;                      // bytes per padded smem row
constexpr int TILEB = 128 * ROWB;             // 10240 B per tile
constexpr int BUFB = 4 * TILEB;               // Ahi,Alo,Bhi,Blo
constexpr int SMEM_GEMM_BYTES = 2 * BUFB;     // double buffer = 81920

__device__ __forceinline__ void load_tile_p(uint32_t dst, const __nv_bfloat16* src,
                                            int row0, int k0, int K, int t) {
    const char* sp = (const char*)(src + (size_t)row0 * K + k0);
    const size_t rs = (size_t)K * 2;
    #pragma unroll
    for (int i = 0; i < 2; i++) {
        int s = i * 256 + t;
        int row = s >> 2, seg = (s & 3) * 16;
        cp_async16(dst + row * ROWB + seg, sp + (size_t)row * rs + seg);
    }
}

template <int MODE>
__global__ __launch_bounds__(256) void gemm_mma(
    const __nv_bfloat16* __restrict__ Ahi, const __nv_bfloat16* __restrict__ Alo,
    const __nv_bfloat16* __restrict__ Bhi, const __nv_bfloat16* __restrict__ Blo,
    const float* __restrict__ bias, float* __restrict__ C, int N, int K)
{
    extern __shared__ char smem[];
    const uint32_t sb = smem_u32(smem);
    const int t = threadIdx.x, wid = t >> 5, lane = t & 31;
    const int warp_m = wid & 3, warp_n = wid >> 2;

    const int rowA = blockIdx.y * 128, rowB = blockIdx.x * 128;
    const int nch = K / 32;

    float acc[2][8][4];
    #pragma unroll
    for (int mt = 0; mt < 2; mt++)
        #pragma unroll
        for (int nt = 0; nt < 8; nt++)
            #pragma unroll
            for (int j = 0; j < 4; j++) acc[mt][nt][j] = 0.f;

    #pragma unroll
    for (int c = 0; c < 2; c++) {
        uint32_t bb = sb + (c & 1) * BUFB;
        load_tile_p(bb + 0 * TILEB, Ahi, rowA, c * 32, K, t);
        load_tile_p(bb + 1 * TILEB, Alo, rowA, c * 32, K, t);
        load_tile_p(bb + 2 * TILEB, Bhi, rowB, c * 32, K, t);
        load_tile_p(bb + 3 * TILEB, Blo, rowB, c * 32, K, t);
        CP_COMMIT();
    }

    // per-lane ldmatrix addressing
    const int lrow = lane & 15;
    const uint32_t lcol = (lane >> 4) << 4;   // byte offset: 0 or 16

    for (int c = 0; c < nch; c++) {
        if (c == nch - 1) { CP_WAIT(0); } else { CP_WAIT(1); }
        __syncthreads();
        const uint32_t bb = sb + (c & 1) * BUFB;
        const uint32_t sAh = bb, sAl = bb + TILEB;
        const uint32_t sBh = bb + 2 * TILEB, sBl = bb + 3 * TILEB;

        #pragma unroll
        for (int kk = 0; kk < 2; kk++) {
            const uint32_t coff = kk * 32 + lcol;
            uint32_t ah[2][4], al[2][4];
            #pragma unroll
            for (int mt = 0; mt < 2; mt++) {
                const uint32_t ro = (warp_m * 32 + mt * 16 + lrow) * ROWB + coff;
                ldm_x4(ah[mt], sAh + ro);
                ldm_x4(al[mt], sAl + ro);
            }
            uint32_t bh[8][2], bl[8][2];
            #pragma unroll
            for (int g = 0; g < 4; g++) {
                const uint32_t ro = (warp_n * 64 + g * 16 + lrow) * ROWB + coff;
                uint32_t r[4];
                ldm_x4(r, sBh + ro);
                bh[2 * g][0] = r[0]; bh[2 * g][1] = r[2];
                bh[2 * g + 1][0] = r[1]; bh[2 * g + 1][1] = r[3];
                ldm_x4(r, sBl + ro);
                bl[2 * g][0] = r[0]; bl[2 * g][1] = r[2];
                bl[2 * g + 1][0] = r[1]; bl[2 * g + 1][1] = r[3];
            }
            #pragma unroll
            for (int mt = 0; mt < 2; mt++)
                #pragma unroll
                for (int nt = 0; nt < 8; nt++) {
                    mma16816(acc[mt][nt], ah[mt], bh[nt]);
                    mma16816(acc[mt][nt], ah[mt], bl[nt]);
                    mma16816(acc[mt][nt], al[mt], bh[nt]);
                }
        }
        __syncthreads();
        if (c + 2 < nch) {
            uint32_t nb = sb + (c & 1) * BUFB;
            load_tile_p(nb + 0 * TILEB, Ahi, rowA, (c + 2) * 32, K, t);
            load_tile_p(nb + 1 * TILEB, Alo, rowA, (c + 2) * 32, K, t);
            load_tile_p(nb + 2 * TILEB, Bhi, rowB, (c + 2) * 32, K, t);
            load_tile_p(nb + 3 * TILEB, Blo, rowB, (c + 2) * 32, K, t);
            CP_COMMIT();
        }
    }

    // epilogue
    #pragma unroll
    for (int mt = 0; mt < 2; mt++) {
        const int r0 = blockIdx.y * 128 + warp_m * 32 + mt * 16 + (lane >> 2);
        #pragma unroll
        for (int nt = 0; nt < 8; nt++) {
            const int col = blockIdx.x * 128 + warp_n * 64 + nt * 8 + (lane & 3) * 2;
            float2 v0 = make_float2(acc[mt][nt][0], acc[mt][nt][1]);
            float2 v1 = make_float2(acc[mt][nt][2], acc[mt][nt][3]);
            if (MODE == 1) {
                const float2 b2 = *(const float2*)(bias + col);
                v0.x += b2.x; v0.y += b2.y;
                v1.x += b2.x; v1.y += b2.y;
            }
            *(float2*)(C + (size_t)r0 * N + col) = v0;
            *(float2*)(C + (size_t)(r0 + 8) * N + col) = v1;
        }
    }
}

// ------------------------- fp32 flash attention ----------------------------
__global__ __launch_bounds__(64) void attn_kernel(
    const float* __restrict__ qkv, float* __restrict__ out)
{
    const int bh = blockIdx.y;
    const int b = bh >> 4, h = bh & 15;
    const int t = threadIdx.x;
    const int i = blockIdx.x * 64 + t;

    const float* base = qkv + (size_t)b * 2048 * 3072;
    const int koff = 1024 + h * 64;
    const int voff = 2048 + h * 64;

    __shared__ float Ks[64][68];
    __shared__ float Vs[64][68];

    float q[64], o[64];
    {
        const float4* qrow = (const float4*)(base + (size_t)i * 3072 + h * 64);
        #pragma unroll
        for (int d4 = 0; d4 < 16; d4++) {
            float4 v = qrow[d4];
            q[d4 * 4 + 0] = v.x; q[d4 * 4 + 1] = v.y;
            q[d4 * 4 + 2] = v.z; q[d4 * 4 + 3] = v.w;
        }
    }
    #pragma unroll
    for (int d = 0; d < 64; d++) o[d] = 0.f;

    float m = -1e30f, l = 0.f;

    for (int j0 = 0; j0 < 2048; j0 += 64) {
        __syncthreads();
        {
            const float4* krow = (const float4*)(base + (size_t)(j0 + t) * 3072 + koff);
            const float4* vrow = (const float4*)(base + (size_t)(j0 + t) * 3072 + voff);
            #pragma unroll
            for (int d4 = 0; d4 < 16; d4++) {
                *(float4*)&Ks[t][d4 * 4] = krow[d4];
                *(float4*)&Vs[t][d4 * 4] = vrow[d4];
            }
        }
        __syncthreads();

        #pragma unroll 1
        for (int c = 0; c < 2; c++) {
            float s[32];
            float cmax = -1e30f;
            #pragma unroll
            for (int jj = 0; jj < 32; jj++) {
                const int j = c * 32 + jj;
                float a0 = 0.f, a1 = 0.f, a2 = 0.f, a3 = 0.f;
                #pragma unroll
                for (int d4 = 0; d4 < 16; d4++) {
                    const float4 kv = *(const float4*)&Ks[j][d4 * 4];
                    a0 = fmaf(q[d4 * 4 + 0], kv.x, a0);
                    a1 = fmaf(q[d4 * 4 + 1], kv.y, a1);
                    a2 = fmaf(q[d4 * 4 + 2], kv.z, a2);
                    a3 = fmaf(q[d4 * 4 + 3], kv.w, a3);
                }
                s[jj] = (a0 + a1) + (a2 + a3);
                cmax = fmaxf(cmax, s[jj]);
            }
            const float mnew = fmaxf(m, cmax);
            const float corr = __expf(m - mnew);
            l *= corr;
            #pragma unroll
            for (int d = 0; d < 64; d++) o[d] *= corr;
            m = mnew;
            #pragma unroll
            for (int jj = 0; jj < 32; jj++) {
                const int j = c * 32 + jj;
                const float p = __expf(s[jj] - m);
                l += p;
                #pragma unroll
                for (int d4 = 0; d4 < 16; d4++) {
                    const float4 vv = *(const float4*)&Vs[j][d4 * 4];
                    o[d4 * 4 + 0] = fmaf(p, vv.x, o[d4 * 4 + 0]);
                    o[d4 * 4 + 1] = fmaf(p, vv.y, o[d4 * 4 + 1]);
                    o[d4 * 4 + 2] = fmaf(p, vv.z, o[d4 * 4 + 2]);
                    o[d4 * 4 + 3] = fmaf(p, vv.w, o[d4 * 4 + 3]);
                }
            }
        }
    }

    const float inv = 1.f / l;
    float* orow = out + (size_t)(b * 2048 + i) * 1024 + h * 64;
    #pragma unroll
    for (int d4 = 0; d4 < 16; d4++) {
        float4 v = make_float4(o[d4 * 4 + 0] * inv, o[d4 * 4 + 1] * inv,
                               o[d4 * 4 + 2] * inv, o[d4 * 4 + 3] * inv);
        *(float4*)&orow[d4 * 4] = v;
    }
}

// ------------------------- launch ------------------------------------------
extern "C" void kernel_launch(void* const* d_in, const int* in_sizes, int n_in,
                              void* d_out, int out_size)
{
    const float* x     = (const float*)d_in[0];
    const float* w_qkv = (const float*)d_in[1];
    const float* w_out = (const float*)d_in[2];
    const float* b_out = (const float*)d_in[3];
    float* out = (float*)d_out;

    float *qkv_p, *att_p;
    __nv_bfloat16 *xhi, *xlo, *wqh, *wql, *woh, *wol, *ahi, *alo;
    cudaGetSymbolAddress((void**)&qkv_p, g_qkv);
    cudaGetSymbolAddress((void**)&att_p, g_att);
    cudaGetSymbolAddress((void**)&xhi, g_xhi);
    cudaGetSymbolAddress((void**)&xlo, g_xlo);
    cudaGetSymbolAddress((void**)&wqh, g_wqkvt_hi);
    cudaGetSymbolAddress((void**)&wql, g_wqkvt_lo);
    cudaGetSymbolAddress((void**)&woh, g_woutt_hi);
    cudaGetSymbolAddress((void**)&wol, g_woutt_lo);
    cudaGetSymbolAddress((void**)&ahi, g_atthi);
    cudaGetSymbolAddress((void**)&alo, g_attlo);

    cudaFuncSetAttribute(gemm_mma<0>, cudaFuncAttributeMaxDynamicSharedMemorySize,
                         SMEM_GEMM_BYTES);
    cudaFuncSetAttribute(gemm_mma<1>, cudaFuncAttributeMaxDynamicSharedMemorySize,
                         SMEM_GEMM_BYTES);

    // prep: bf16 splits + weight transposes (scale folded into q-cols of w_qkv)
    split_fp32<<<(8192 * 1024 / 4 + 255) / 256, 256>>>(x, xhi, xlo, 8192 * 1024 / 4);
    transpose_split<<<dim3(3072 / 32, 1024 / 32), dim3(32, 8)>>>(
        w_qkv, wqh, wql, 1024, 3072, 1024);
    transpose_split<<<dim3(1024 / 32, 1024 / 32), dim3(32, 8)>>>(
        w_out, woh, wol, 1024, 1024, 0);

    // stage 1: qkv = x @ w_qkv
    gemm_mma<0><<<dim3(3072 / 128, 8192 / 128), 256, SMEM_GEMM_BYTES>>>(
        xhi, xlo, wqh, wql, nullptr, qkv_p, 3072, 1024);

    // stage 2: attention
    attn_kernel<<<dim3(2048 / 64, 64), 64>>>(qkv_p, att_p);

    // stage 3: out = att @ w_out + b
    split_fp32<<<(8192 * 1024 / 4 + 255) / 256, 256>>>(att_p, ahi, alo, 8192 * 1024 / 4);
    gemm_mma<1><<<dim3(1024 / 128, 8192 / 128), 256, SMEM_GEMM_BYTES>>>(
        ahi, alo, woh, wol, b_out, out, 1024, 1024);
}

// round 5
// speedup vs baseline: 1.2579x; 1.0077x over previous
#include <cuda_runtime.h>
#include <cuda_bf16.h>
#include <cstdint>

// ---------------------------------------------------------------------------
// Attention_71485435675049 — Round 4 (resubmit of R3; infra failure, no data)
// Stage 1/3 GEMMs on mma.sync m16n8k16 bf16 (hi/lo split, fp32 accum).
// (tcgen05 rejected: harness ptxas targets plain sm_100, no 'a' features.)
// Stage 2 attention: fp32 flash (unchanged; HMMA next round).
// ---------------------------------------------------------------------------

#define ATT_SCALE 0.125f

// ------------------------- scratch (no allocs allowed) ----------------------
__device__ float g_qkv[8192 * 3072];
__device__ float g_att[8192 * 1024];
__device__ __nv_bfloat16 g_xhi[8192 * 1024];
__device__ __nv_bfloat16 g_xlo[8192 * 1024];
__device__ __nv_bfloat16 g_wqkvt_hi[3072 * 1024];   // [N,K] transposed
__device__ __nv_bfloat16 g_wqkvt_lo[3072 * 1024];
__device__ __nv_bfloat16 g_woutt_hi[1024 * 1024];
__device__ __nv_bfloat16 g_woutt_lo[1024 * 1024];
__device__ __nv_bfloat16 g_atthi[8192 * 1024];
__device__ __nv_bfloat16 g_attlo[8192 * 1024];

// ------------------------- PTX helpers -------------------------------------
__device__ __forceinline__ uint32_t smem_u32(const void* p) {
    uint32_t a;
    asm("{ .reg .u64 t; cvta.to.shared.u64 t, %1; cvt.u32.u64 %0, t; }"
        : "=r"(a) : "l"(p));
    return a;
}

__device__ __forceinline__ void cp_async16(uint32_t dst, const void* src) {
    asm volatile("cp.async.cg.shared.global [%0], [%1], 16;\n"
                 :: "r"(dst), "l"(src));
}
#define CP_COMMIT() asm volatile("cp.async.commit_group;\n" ::: "memory")
#define CP_WAIT(n)  asm volatile("cp.async.wait_group %0;\n" :: "n"(n) : "memory")

__device__ __forceinline__ void ldm_x4(uint32_t r[4], uint32_t addr) {
    asm volatile("ldmatrix.sync.aligned.m8n8.x4.shared.b16 {%0,%1,%2,%3}, [%4];"
                 : "=r"(r[0]), "=r"(r[1]), "=r"(r[2]), "=r"(r[3]) : "r"(addr));
}

__device__ __forceinline__ void mma16816(float c[4], const uint32_t a[4],
                                         const uint32_t b[2]) {
    asm volatile(
        "mma.sync.aligned.m16n8k16.row.col.f32.bf16.bf16.f32 "
        "{%0,%1,%2,%3}, {%4,%5,%6,%7}, {%8,%9}, {%0,%1,%2,%3};"
        : "+f"(c[0]), "+f"(c[1]), "+f"(c[2]), "+f"(c[3])
        : "r"(a[0]), "r"(a[1]), "r"(a[2]), "r"(a[3]), "r"(b[0]), "r"(b[1]));
}

// ------------------------- conversion kernels ------------------------------
__global__ void split_fp32(const float* __restrict__ src,
                           __nv_bfloat16* __restrict__ hi,
                           __nv_bfloat16* __restrict__ lo, int n4) {
    int i = blockIdx.x * blockDim.x + threadIdx.x;
    if (i >= n4) return;
    float4 v = ((const float4*)src)[i];
    __nv_bfloat16 h0 = __float2bfloat16(v.x), h1 = __float2bfloat16(v.y);
    __nv_bfloat16 h2 = __float2bfloat16(v.z), h3 = __float2bfloat16(v.w);
    hi[i * 4 + 0] = h0; hi[i * 4 + 1] = h1; hi[i * 4 + 2] = h2; hi[i * 4 + 3] = h3;
    lo[i * 4 + 0] = __float2bfloat16(v.x - __bfloat162float(h0));
    lo[i * 4 + 1] = __float2bfloat16(v.y - __bfloat162float(h1));
    lo[i * 4 + 2] = __float2bfloat16(v.z - __bfloat162float(h2));
    lo[i * 4 + 3] = __float2bfloat16(v.w - __bfloat162float(h3));
}

// src[K,N] fp32 -> out[N,K] bf16 hi/lo; cols < scale_cols scaled by ATT_SCALE
__global__ void transpose_split(const float* __restrict__ src,
                                __nv_bfloat16* __restrict__ hi,
                                __nv_bfloat16* __restrict__ lo,
                                int K, int N, int scale_cols) {
    __shared__ float tile[32][33];
    const int n0 = blockIdx.x * 32, k0 = blockIdx.y * 32;
    const int tx = threadIdx.x, ty = threadIdx.y;
    #pragma unroll
    for (int j = 0; j < 4; j++) {
        int r = ty + j * 8;
        float v = src[(size_t)(k0 + r) * N + n0 + tx];
        if (n0 + tx < scale_cols) v *= ATT_SCALE;
        tile[r][tx] = v;
    }
    __syncthreads();
    #pragma unroll
    for (int j = 0; j < 4; j++) {
        int b = ty + j * 8;
        float v = tile[tx][b];
        __nv_bfloat16 h = __float2bfloat16(v);
        size_t o = (size_t)(n0 + b) * K + k0 + tx;
        hi[o] = h;
        lo[o] = __float2bfloat16(v - __bfloat162float(h));
    }
}

// ------------------------- HMMA GEMM ---------------------------------------
// C[M,N] = (Ahi+Alo)[M,K] @ (Bhi+Blo)[N,K]^T, 3-term split, fp32 accum.
// Tile 128x128, BK=32, 256 threads (warps 4x2 -> 32x64 warp tiles).
// Smem rows padded to 40 bf16 (80B): conflict-free ldmatrix + STS.
constexpr int ROWB = 80;                      // bytes per padded smem row
constexpr int TILEB = 128 * ROWB;             // 10240 B per tile
constexpr int BUFB = 4 * TILEB;               // Ahi,Alo,Bhi,Blo
constexpr int SMEM_GEMM_BYTES = 2 * BUFB;     // double buffer = 81920

__device__ __forceinline__ void load_tile_p(uint32_t dst, const __nv_bfloat16* src,
                                            int row0, int k0, int K, int t) {
    const char* sp = (const char*)(src + (size_t)row0 * K + k0);
    const size_t rs = (size_t)K * 2;
    #pragma unroll
    for (int i = 0; i < 2; i++) {
        int s = i * 256 + t;
        int row = s >> 2, seg = (s & 3) * 16;
        cp_async16(dst + row * ROWB + seg, sp + (size_t)row * rs + seg);
    }
}

template <int MODE>
__global__ __launch_bounds__(256) void gemm_mma(
    const __nv_bfloat16* __restrict__ Ahi, const __nv_bfloat16* __restrict__ Alo,
    const __nv_bfloat16* __restrict__ Bhi, const __nv_bfloat16* __restrict__ Blo,
    const float* __restrict__ bias, float* __restrict__ C, int N, int K)
{
    extern __shared__ char smem[];
    const uint32_t sb = smem_u32(smem);
    const int t = threadIdx.x, wid = t >> 5, lane = t & 31;
    const int warp_m = wid & 3, warp_n = wid >> 2;

    const int rowA = blockIdx.y * 128, rowB = blockIdx.x * 128;
    const int nch = K / 32;

    float acc[2][8][4];
    #pragma unroll
    for (int mt = 0; mt < 2; mt++)
        #pragma unroll
        for (int nt = 0; nt < 8; nt++)
            #pragma unroll
            for (int j = 0; j < 4; j++) acc[mt][nt][j] = 0.f;

    #pragma unroll
    for (int c = 0; c < 2; c++) {
        uint32_t bb = sb + (c & 1) * BUFB;
        load_tile_p(bb + 0 * TILEB, Ahi, rowA, c * 32, K, t);
        load_tile_p(bb + 1 * TILEB, Alo, rowA, c * 32, K, t);
        load_tile_p(bb + 2 * TILEB, Bhi, rowB, c * 32, K, t);
        load_tile_p(bb + 3 * TILEB, Blo, rowB, c * 32, K, t);
        CP_COMMIT();
    }

    // per-lane ldmatrix addressing
    const int lrow = lane & 15;
    const uint32_t lcol = (lane >> 4) << 4;   // byte offset: 0 or 16

    for (int c = 0; c < nch; c++) {
        if (c == nch - 1) { CP_WAIT(0); } else { CP_WAIT(1); }
        __syncthreads();
        const uint32_t bb = sb + (c & 1) * BUFB;
        const uint32_t sAh = bb, sAl = bb + TILEB;
        const uint32_t sBh = bb + 2 * TILEB, sBl = bb + 3 * TILEB;

        #pragma unroll
        for (int kk = 0; kk < 2; kk++) {
            const uint32_t coff = kk * 32 + lcol;
            uint32_t ah[2][4], al[2][4];
            #pragma unroll
            for (int mt = 0; mt < 2; mt++) {
                const uint32_t ro = (warp_m * 32 + mt * 16 + lrow) * ROWB + coff;
                ldm_x4(ah[mt], sAh + ro);
                ldm_x4(al[mt], sAl + ro);
            }
            uint32_t bh[8][2], bl[8][2];
            #pragma unroll
            for (int g = 0; g < 4; g++) {
                const uint32_t ro = (warp_n * 64 + g * 16 + lrow) * ROWB + coff;
                uint32_t r[4];
                ldm_x4(r, sBh + ro);
                bh[2 * g][0] = r[0]; bh[2 * g][1] = r[2];
                bh[2 * g + 1][0] = r[1]; bh[2 * g + 1][1] = r[3];
                ldm_x4(r, sBl + ro);
                bl[2 * g][0] = r[0]; bl[2 * g][1] = r[2];
                bl[2 * g + 1][0] = r[1]; bl[2 * g + 1][1] = r[3];
            }
            #pragma unroll
            for (int mt = 0; mt < 2; mt++)
                #pragma unroll
                for (int nt = 0; nt < 8; nt++) {
                    mma16816(acc[mt][nt], ah[mt], bh[nt]);
                    mma16816(acc[mt][nt], ah[mt], bl[nt]);
                    mma16816(acc[mt][nt], al[mt], bh[nt]);
                }
        }
        __syncthreads();
        if (c + 2 < nch) {
            uint32_t nb = sb + (c & 1) * BUFB;
            load_tile_p(nb + 0 * TILEB, Ahi, rowA, (c + 2) * 32, K, t);
            load_tile_p(nb + 1 * TILEB, Alo, rowA, (c + 2) * 32, K, t);
            load_tile_p(nb + 2 * TILEB, Bhi, rowB, (c + 2) * 32, K, t);
            load_tile_p(nb + 3 * TILEB, Blo, rowB, (c + 2) * 32, K, t);
            CP_COMMIT();
        }
    }

    // epilogue
    #pragma unroll
    for (int mt = 0; mt < 2; mt++) {
        const int r0 = blockIdx.y * 128 + warp_m * 32 + mt * 16 + (lane >> 2);
        #pragma unroll
        for (int nt = 0; nt < 8; nt++) {
            const int col = blockIdx.x * 128 + warp_n * 64 + nt * 8 + (lane & 3) * 2;
            float2 v0 = make_float2(acc[mt][nt][0], acc[mt][nt][1]);
            float2 v1 = make_float2(acc[mt][nt][2], acc[mt][nt][3]);
            if (MODE == 1) {
                const float2 b2 = *(const float2*)(bias + col);
                v0.x += b2.x; v0.y += b2.y;
                v1.x += b2.x; v1.y += b2.y;
            }
            *(float2*)(C + (size_t)r0 * N + col) = v0;
            *(float2*)(C + (size_t)(r0 + 8) * N + col) = v1;
        }
    }
}

// ------------------------- fp32 flash attention ----------------------------
__global__ __launch_bounds__(64) void attn_kernel(
    const float* __restrict__ qkv, float* __restrict__ out)
{
    const int bh = blockIdx.y;
    const int b = bh >> 4, h = bh & 15;
    const int t = threadIdx.x;
    const int i = blockIdx.x * 64 + t;

    const float* base = qkv + (size_t)b * 2048 * 3072;
    const int koff = 1024 + h * 64;
    const int voff = 2048 + h * 64;

    __shared__ float Ks[64][68];
    __shared__ float Vs[64][68];

    float q[64], o[64];
    {
        const float4* qrow = (const float4*)(base + (size_t)i * 3072 + h * 64);
        #pragma unroll
        for (int d4 = 0; d4 < 16; d4++) {
            float4 v = qrow[d4];
            q[d4 * 4 + 0] = v.x; q[d4 * 4 + 1] = v.y;
            q[d4 * 4 + 2] = v.z; q[d4 * 4 + 3] = v.w;
        }
    }
    #pragma unroll
    for (int d = 0; d < 64; d++) o[d] = 0.f;

    float m = -1e30f, l = 0.f;

    for (int j0 = 0; j0 < 2048; j0 += 64) {
        __syncthreads();
        {
            const float4* krow = (const float4*)(base + (size_t)(j0 + t) * 3072 + koff);
            const float4* vrow = (const float4*)(base + (size_t)(j0 + t) * 3072 + voff);
            #pragma unroll
            for (int d4 = 0; d4 < 16; d4++) {
                *(float4*)&Ks[t][d4 * 4] = krow[d4];
                *(float4*)&Vs[t][d4 * 4] = vrow[d4];
            }
        }
        __syncthreads();

        #pragma unroll 1
        for (int c = 0; c < 2; c++) {
            float s[32];
            float cmax = -1e30f;
            #pragma unroll
            for (int jj = 0; jj < 32; jj++) {
                const int j = c * 32 + jj;
                float a0 = 0.f, a1 = 0.f, a2 = 0.f, a3 = 0.f;
                #pragma unroll
                for (int d4 = 0; d4 < 16; d4++) {
                    const float4 kv = *(const float4*)&Ks[j][d4 * 4];
                    a0 = fmaf(q[d4 * 4 + 0], kv.x, a0);
                    a1 = fmaf(q[d4 * 4 + 1], kv.y, a1);
                    a2 = fmaf(q[d4 * 4 + 2], kv.z, a2);
                    a3 = fmaf(q[d4 * 4 + 3], kv.w, a3);
                }
                s[jj] = (a0 + a1) + (a2 + a3);
                cmax = fmaxf(cmax, s[jj]);
            }
            const float mnew = fmaxf(m, cmax);
            const float corr = __expf(m - mnew);
            l *= corr;
            #pragma unroll
            for (int d = 0; d < 64; d++) o[d] *= corr;
            m = mnew;
            #pragma unroll
            for (int jj = 0; jj < 32; jj++) {
                const int j = c * 32 + jj;
                const float p = __expf(s[jj] - m);
                l += p;
                #pragma unroll
                for (int d4 = 0; d4 < 16; d4++) {
                    const float4 vv = *(const float4*)&Vs[j][d4 * 4];
                    o[d4 * 4 + 0] = fmaf(p, vv.x, o[d4 * 4 + 0]);
                    o[d4 * 4 + 1] = fmaf(p, vv.y, o[d4 * 4 + 1]);
                    o[d4 * 4 + 2] = fmaf(p, vv.z, o[d4 * 4 + 2]);
                    o[d4 * 4 + 3] = fmaf(p, vv.w, o[d4 * 4 + 3]);
                }
            }
        }
    }

    const float inv = 1.f / l;
    float* orow = out + (size_t)(b * 2048 + i) * 1024 + h * 64;
    #pragma unroll
    for (int d4 = 0; d4 < 16; d4++) {
        float4 v = make_float4(o[d4 * 4 + 0] * inv, o[d4 * 4 + 1] * inv,
                               o[d4 * 4 + 2] * inv, o[d4 * 4 + 3] * inv);
        *(float4*)&orow[d4 * 4] = v;
    }
}

// ------------------------- launch ------------------------------------------
extern "C" void kernel_launch(void* const* d_in, const int* in_sizes, int n_in,
                              void* d_out, int out_size)
{
    const float* x     = (const float*)d_in[0];
    const float* w_qkv = (const float*)d_in[1];
    const float* w_out = (const float*)d_in[2];
    const float* b_out = (const float*)d_in[3];
    float* out = (float*)d_out;

    float *qkv_p, *att_p;
    __nv_bfloat16 *xhi, *xlo, *wqh, *wql, *woh, *wol, *ahi, *alo;
    cudaGetSymbolAddress((void**)&qkv_p, g_qkv);
    cudaGetSymbolAddress((void**)&att_p, g_att);
    cudaGetSymbolAddress((void**)&xhi, g_xhi);
    cudaGetSymbolAddress((void**)&xlo, g_xlo);
    cudaGetSymbolAddress((void**)&wqh, g_wqkvt_hi);
    cudaGetSymbolAddress((void**)&wql, g_wqkvt_lo);
    cudaGetSymbolAddress((void**)&woh, g_woutt_hi);
    cudaGetSymbolAddress((void**)&wol, g_woutt_lo);
    cudaGetSymbolAddress((void**)&ahi, g_atthi);
    cudaGetSymbolAddress((void**)&alo, g_attlo);

    cudaFuncSetAttribute(gemm_mma<0>, cudaFuncAttributeMaxDynamicSharedMemorySize,
                         SMEM_GEMM_BYTES);
    cudaFuncSetAttribute(gemm_mma<1>, cudaFuncAttributeMaxDynamicSharedMemorySize,
                         SMEM_GEMM_BYTES);

    // prep: bf16 splits + weight transposes (scale folded into q-cols of w_qkv)
    split_fp32<<<(8192 * 1024 / 4 + 255) / 256, 256>>>(x, xhi, xlo, 8192 * 1024 / 4);
    transpose_split<<<dim3(3072 / 32, 1024 / 32), dim3(32, 8)>>>(
        w_qkv, wqh, wql, 1024, 3072, 1024);
    transpose_split<<<dim3(1024 / 32, 1024 / 32), dim3(32, 8)>>>(
        w_out, woh, wol, 1024, 1024, 0);

    // stage 1: qkv = x @ w_qkv
    gemm_mma<0><<<dim3(3072 / 128, 8192 / 128), 256, SMEM_GEMM_BYTES>>>(
        xhi, xlo, wqh, wql, nullptr, qkv_p, 3072, 1024);

    // stage 2: attention
    attn_kernel<<<dim3(2048 / 64, 64), 64>>>(qkv_p, att_p);

    // stage 3: out = att @ w_out + b
    split_fp32<<<(8192 * 1024 / 4 + 255) / 256, 256>>>(att_p, ahi, alo, 8192 * 1024 / 4);
    gemm_mma<1><<<dim3(1024 / 128, 8192 / 128), 256, SMEM_GEMM_BYTES>>>(
        ahi, alo, woh, wol, b_out, out, 1024, 1024);
}

// round 6
// speedup vs baseline: 3.7064x; 2.9465x over previous
#include <cuda_runtime.h>
#include <cuda_bf16.h>
#include <cstdint>

// ---------------------------------------------------------------------------
// Attention_71485435675049 — Round 6
// All three stages on mma.sync m16n8k16 bf16 (hi/lo split, fp32 accum).
// GEMM-0 writes split qkv directly; flash-attn writes split att directly.
// ---------------------------------------------------------------------------

#define ATT_SCALE 0.125f
#define LOG2E 1.4426950408889634f

// ------------------------- scratch (no allocs allowed) ----------------------
__device__ __nv_bfloat16 g_xhi[8192 * 1024];
__device__ __nv_bfloat16 g_xlo[8192 * 1024];
__device__ __nv_bfloat16 g_wqkvt_hi[3072 * 1024];   // [N,K] transposed
__device__ __nv_bfloat16 g_wqkvt_lo[3072 * 1024];
__device__ __nv_bfloat16 g_woutt_hi[1024 * 1024];
__device__ __nv_bfloat16 g_woutt_lo[1024 * 1024];
__device__ __nv_bfloat16 g_qkvhi[8192 * 3072];
__device__ __nv_bfloat16 g_qkvlo[8192 * 3072];
__device__ __nv_bfloat16 g_atthi[8192 * 1024];
__device__ __nv_bfloat16 g_attlo[8192 * 1024];

// ------------------------- PTX helpers -------------------------------------
__device__ __forceinline__ uint32_t smem_u32(const void* p) {
    uint32_t a;
    asm("{ .reg .u64 t; cvta.to.shared.u64 t, %1; cvt.u32.u64 %0, t; }"
        : "=r"(a) : "l"(p));
    return a;
}

__device__ __forceinline__ void cp_async16(uint32_t dst, const void* src) {
    asm volatile("cp.async.cg.shared.global [%0], [%1], 16;\n"
                 :: "r"(dst), "l"(src));
}
#define CP_COMMIT() asm volatile("cp.async.commit_group;\n" ::: "memory")
#define CP_WAIT(n)  asm volatile("cp.async.wait_group %0;\n" :: "n"(n) : "memory")

__device__ __forceinline__ void ldm_x4(uint32_t r[4], uint32_t addr) {
    asm volatile("ldmatrix.sync.aligned.m8n8.x4.shared.b16 {%0,%1,%2,%3}, [%4];"
                 : "=r"(r[0]), "=r"(r[1]), "=r"(r[2]), "=r"(r[3]) : "r"(addr));
}
__device__ __forceinline__ void ldm_x4_t(uint32_t r[4], uint32_t addr) {
    asm volatile("ldmatrix.sync.aligned.m8n8.x4.trans.shared.b16 {%0,%1,%2,%3}, [%4];"
                 : "=r"(r[0]), "=r"(r[1]), "=r"(r[2]), "=r"(r[3]) : "r"(addr));
}

__device__ __forceinline__ void mma16816(float c[4], const uint32_t a[4],
                                         const uint32_t b[2]) {
    asm volatile(
        "mma.sync.aligned.m16n8k16.row.col.f32.bf16.bf16.f32 "
        "{%0,%1,%2,%3}, {%4,%5,%6,%7}, {%8,%9}, {%0,%1,%2,%3};"
        : "+f"(c[0]), "+f"(c[1]), "+f"(c[2]), "+f"(c[3])
        : "r"(a[0]), "r"(a[1]), "r"(a[2]), "r"(a[3]), "r"(b[0]), "r"(b[1]));
}

__device__ __forceinline__ float ex2(float x) {
    float r; asm("ex2.approx.f32 %0, %1;" : "=f"(r) : "f"(x)); return r;
}
__device__ __forceinline__ uint32_t prmt_hihi(uint32_t a, uint32_t b) {
    uint32_t d;
    asm("prmt.b32 %0, %1, %2, 0x7632;" : "=r"(d) : "r"(a), "r"(b));
    return d;
}
__device__ __forceinline__ uint32_t pack_bf16x2_rn(float lo, float hi) {
    uint32_t d;
    asm("cvt.rn.bf16x2.f32 %0, %1, %2;" : "=r"(d) : "f"(hi), "f"(lo));
    return d;
}

// ------------------------- conversion kernels ------------------------------
__global__ void split_fp32(const float* __restrict__ src,
                           __nv_bfloat16* __restrict__ hi,
                           __nv_bfloat16* __restrict__ lo, int n4) {
    int i = blockIdx.x * blockDim.x + threadIdx.x;
    if (i >= n4) return;
    float4 v = ((const float4*)src)[i];
    __nv_bfloat16 h0 = __float2bfloat16(v.x), h1 = __float2bfloat16(v.y);
    __nv_bfloat16 h2 = __float2bfloat16(v.z), h3 = __float2bfloat16(v.w);
    hi[i * 4 + 0] = h0; hi[i * 4 + 1] = h1; hi[i * 4 + 2] = h2; hi[i * 4 + 3] = h3;
    lo[i * 4 + 0] = __float2bfloat16(v.x - __bfloat162float(h0));
    lo[i * 4 + 1] = __float2bfloat16(v.y - __bfloat162float(h1));
    lo[i * 4 + 2] = __float2bfloat16(v.z - __bfloat162float(h2));
    lo[i * 4 + 3] = __float2bfloat16(v.w - __bfloat162float(h3));
}

// src[K,N] fp32 -> out[N,K] bf16 hi/lo; cols < scale_cols scaled by `scale`
__global__ void transpose_split(const float* __restrict__ src,
                                __nv_bfloat16* __restrict__ hi,
                                __nv_bfloat16* __restrict__ lo,
                                int K, int N, int scale_cols, float scale) {
    __shared__ float tile[32][33];
    const int n0 = blockIdx.x * 32, k0 = blockIdx.y * 32;
    const int tx = threadIdx.x, ty = threadIdx.y;
    #pragma unroll
    for (int j = 0; j < 4; j++) {
        int r = ty + j * 8;
        float v = src[(size_t)(k0 + r) * N + n0 + tx];
        if (n0 + tx < scale_cols) v *= scale;
        tile[r][tx] = v;
    }
    __syncthreads();
    #pragma unroll
    for (int j = 0; j < 4; j++) {
        int b = ty + j * 8;
        float v = tile[tx][b];
        __nv_bfloat16 h = __float2bfloat16(v);
        size_t o = (size_t)(n0 + b) * K + k0 + tx;
        hi[o] = h;
        lo[o] = __float2bfloat16(v - __bfloat162float(h));
    }
}

// ------------------------- HMMA GEMM ---------------------------------------
// Tile 128x128, BK=32, 256 threads (warps 4x2 -> 32x64 warp tiles).
// MODE 0: write split bf16 hi/lo outputs. MODE 1: write fp32 + bias.
constexpr int ROWB = 80;
constexpr int TILEB = 128 * ROWB;
constexpr int BUFB = 4 * TILEB;
constexpr int SMEM_GEMM_BYTES = 2 * BUFB;     // 81920

__device__ __forceinline__ void load_tile_p(uint32_t dst, const __nv_bfloat16* src,
                                            int row0, int k0, int K, int t) {
    const char* sp = (const char*)(src + (size_t)row0 * K + k0);
    const size_t rs = (size_t)K * 2;
    #pragma unroll
    for (int i = 0; i < 2; i++) {
        int s = i * 256 + t;
        int row = s >> 2, seg = (s & 3) * 16;
        cp_async16(dst + row * ROWB + seg, sp + (size_t)row * rs + seg);
    }
}

template <int MODE>
__global__ __launch_bounds__(256) void gemm_mma(
    const __nv_bfloat16* __restrict__ Ahi, const __nv_bfloat16* __restrict__ Alo,
    const __nv_bfloat16* __restrict__ Bhi, const __nv_bfloat16* __restrict__ Blo,
    const float* __restrict__ bias,
    __nv_bfloat16* __restrict__ Chi, __nv_bfloat16* __restrict__ Clo,
    float* __restrict__ Cf, int N, int K)
{
    extern __shared__ char smem[];
    const uint32_t sb = smem_u32(smem);
    const int t = threadIdx.x, wid = t >> 5, lane = t & 31;
    const int warp_m = wid & 3, warp_n = wid >> 2;

    const int rowA = blockIdx.y * 128, rowB = blockIdx.x * 128;
    const int nch = K / 32;

    float acc[2][8][4];
    #pragma unroll
    for (int mt = 0; mt < 2; mt++)
        #pragma unroll
        for (int nt = 0; nt < 8; nt++)
            #pragma unroll
            for (int j = 0; j < 4; j++) acc[mt][nt][j] = 0.f;

    #pragma unroll
    for (int c = 0; c < 2; c++) {
        uint32_t bb = sb + (c & 1) * BUFB;
        load_tile_p(bb + 0 * TILEB, Ahi, rowA, c * 32, K, t);
        load_tile_p(bb + 1 * TILEB, Alo, rowA, c * 32, K, t);
        load_tile_p(bb + 2 * TILEB, Bhi, rowB, c * 32, K, t);
        load_tile_p(bb + 3 * TILEB, Blo, rowB, c * 32, K, t);
        CP_COMMIT();
    }

    const int lrow = lane & 15;
    const uint32_t lcol = (lane >> 4) << 4;

    for (int c = 0; c < nch; c++) {
        if (c == nch - 1) { CP_WAIT(0); } else { CP_WAIT(1); }
        __syncthreads();
        const uint32_t bb = sb + (c & 1) * BUFB;
        const uint32_t sAh = bb, sAl = bb + TILEB;
        const uint32_t sBh = bb + 2 * TILEB, sBl = bb + 3 * TILEB;

        #pragma unroll
        for (int kk = 0; kk < 2; kk++) {
            const uint32_t coff = kk * 32 + lcol;
            uint32_t ah[2][4], al[2][4];
            #pragma unroll
            for (int mt = 0; mt < 2; mt++) {
                const uint32_t ro = (warp_m * 32 + mt * 16 + lrow) * ROWB + coff;
                ldm_x4(ah[mt], sAh + ro);
                ldm_x4(al[mt], sAl + ro);
            }
            uint32_t bh[8][2], bl[8][2];
            #pragma unroll
            for (int g = 0; g < 4; g++) {
                const uint32_t ro = (warp_n * 64 + g * 16 + lrow) * ROWB + coff;
                uint32_t r[4];
                ldm_x4(r, sBh + ro);
                bh[2 * g][0] = r[0]; bh[2 * g][1] = r[2];
                bh[2 * g + 1][0] = r[1]; bh[2 * g + 1][1] = r[3];
                ldm_x4(r, sBl + ro);
                bl[2 * g][0] = r[0]; bl[2 * g][1] = r[2];
                bl[2 * g + 1][0] = r[1]; bl[2 * g + 1][1] = r[3];
            }
            #pragma unroll
            for (int mt = 0; mt < 2; mt++)
                #pragma unroll
                for (int nt = 0; nt < 8; nt++) {
                    mma16816(acc[mt][nt], ah[mt], bh[nt]);
                    mma16816(acc[mt][nt], ah[mt], bl[nt]);
                    mma16816(acc[mt][nt], al[mt], bh[nt]);
                }
        }
        __syncthreads();
        if (c + 2 < nch) {
            uint32_t nb = sb + (c & 1) * BUFB;
            load_tile_p(nb + 0 * TILEB, Ahi, rowA, (c + 2) * 32, K, t);
            load_tile_p(nb + 1 * TILEB, Alo, rowA, (c + 2) * 32, K, t);
            load_tile_p(nb + 2 * TILEB, Bhi, rowB, (c + 2) * 32, K, t);
            load_tile_p(nb + 3 * TILEB, Blo, rowB, (c + 2) * 32, K, t);
            CP_COMMIT();
        }
    }

    // epilogue
    #pragma unroll
    for (int mt = 0; mt < 2; mt++) {
        const int r0 = blockIdx.y * 128 + warp_m * 32 + mt * 16 + (lane >> 2);
        #pragma unroll
        for (int nt = 0; nt < 8; nt++) {
            const int col = blockIdx.x * 128 + warp_n * 64 + nt * 8 + (lane & 3) * 2;
            if (MODE == 1) {
                const float2 b2 = *(const float2*)(bias + col);
                *(float2*)(Cf + (size_t)r0 * N + col) =
                    make_float2(acc[mt][nt][0] + b2.x, acc[mt][nt][1] + b2.y);
                *(float2*)(Cf + (size_t)(r0 + 8) * N + col) =
                    make_float2(acc[mt][nt][2] + b2.x, acc[mt][nt][3] + b2.y);
            } else {
                #pragma unroll
                for (int hrow = 0; hrow < 2; hrow++) {
                    const float v0 = acc[mt][nt][hrow * 2];
                    const float v1 = acc[mt][nt][hrow * 2 + 1];
                    __nv_bfloat162 h = __float22bfloat162_rn(make_float2(v0, v1));
                    __nv_bfloat162 l = __float22bfloat162_rn(
                        make_float2(v0 - __low2float(h), v1 - __high2float(h)));
                    const size_t off = (size_t)(r0 + 8 * hrow) * N + col;
                    *(__nv_bfloat162*)(Chi + off) = h;
                    *(__nv_bfloat162*)(Clo + off) = l;
                }
            }
        }
    }
}

// ------------------------- HMMA flash attention ----------------------------
// Block: 256 thr (8 warps), q-tile 128 (16 rows/warp), key-tiles of 64.
// smem rows padded to 144B (conflict-free ldmatrix at 128B data width).
constexpr int AROWB = 144;
constexpr int QTILEB = 128 * AROWB;            // 18432
constexpr int KTILEB = 64 * AROWB;             // 9216
constexpr int KVBUF = 4 * KTILEB;              // KH,KL,VH,VL = 36864
constexpr int SMEM_ATT_BYTES = 2 * QTILEB + 2 * KVBUF;  // 110592

__device__ __forceinline__ void att_load(uint32_t dst, const __nv_bfloat16* src,
                                         int rows256, int t) {
    // rows256: number of (row,seg) pairs / 256. src row stride = 3072 elems.
    #pragma unroll
    for (int i = 0; i < 4; i++) {
        if (i >= rows256) break;
        int s = i * 256 + t;
        int r = s >> 3, seg = (s & 7) * 16;
        cp_async16(dst + r * AROWB + seg, (const char*)src + (size_t)r * 6144 + seg);
    }
}

__global__ __launch_bounds__(256) void attn_mma(
    const __nv_bfloat16* __restrict__ qkvh, const __nv_bfloat16* __restrict__ qkvl,
    __nv_bfloat16* __restrict__ outhi, __nv_bfloat16* __restrict__ outlo)
{
    extern __shared__ char smem[];
    const uint32_t sb = smem_u32(smem);
    const int t = threadIdx.x, wid = t >> 5, lane = t & 31;
    const int bh = blockIdx.y, b = bh >> 4, h = bh & 15;
    const int q0 = blockIdx.x * 128;
    const size_t rb = (size_t)b * 2048;

    const uint32_t QH = sb, QL = sb + QTILEB;
    const __nv_bfloat16* kh_b = qkvh + rb * 3072 + 1024 + h * 64;
    const __nv_bfloat16* kl_b = qkvl + rb * 3072 + 1024 + h * 64;
    const __nv_bfloat16* vh_b = qkvh + rb * 3072 + 2048 + h * 64;
    const __nv_bfloat16* vl_b = qkvl + rb * 3072 + 2048 + h * 64;

    // Q + first two K/V buffers
    att_load(QH, qkvh + (rb + q0) * 3072 + h * 64, 4, t);
    att_load(QL, qkvl + (rb + q0) * 3072 + h * 64, 4, t);
    #pragma unroll
    for (int c = 0; c < 2; c++) {
        const uint32_t kb = sb + 2 * QTILEB + c * KVBUF;
        att_load(kb + 0 * KTILEB, kh_b + (size_t)(c * 64) * 3072, 2, t);
        att_load(kb + 1 * KTILEB, kl_b + (size_t)(c * 64) * 3072, 2, t);
        att_load(kb + 2 * KTILEB, vh_b + (size_t)(c * 64) * 3072, 2, t);
        att_load(kb + 3 * KTILEB, vl_b + (size_t)(c * 64) * 3072, 2, t);
        CP_COMMIT();
    }

    float oacc[8][4];
    #pragma unroll
    for (int nd = 0; nd < 8; nd++)
        #pragma unroll
        for (int j = 0; j < 4; j++) oacc[nd][j] = 0.f;
    float m0 = -1e30f, m1 = -1e30f, l0 = 0.f, l1 = 0.f;

    const int lrow = lane & 15;
    const uint32_t lcol = (lane >> 4) << 4;

    for (int c = 0; c < 32; c++) {
        if (c == 31) { CP_WAIT(0); } else { CP_WAIT(1); }
        __syncthreads();
        const uint32_t kb = sb + 2 * QTILEB + (c & 1) * KVBUF;
        const uint32_t sKh = kb, sKl = kb + KTILEB;
        const uint32_t sVh = kb + 2 * KTILEB, sVl = kb + 3 * KTILEB;

        // ---- S = Q K^T (3-term) ----
        float sacc[8][4];
        #pragma unroll
        for (int nt = 0; nt < 8; nt++)
            #pragma unroll
            for (int j = 0; j < 4; j++) sacc[nt][j] = 0.f;

        #pragma unroll
        for (int kt = 0; kt < 4; kt++) {
            const uint32_t coff = kt * 32 + lcol;
            uint32_t qh4[4], ql4[4];
            const uint32_t qro = (wid * 16 + lrow) * AROWB + coff;
            ldm_x4(qh4, QH + qro);
            ldm_x4(ql4, QL + qro);
            uint32_t bh[8][2], bl[8][2];
            #pragma unroll
            for (int g = 0; g < 4; g++) {
                const uint32_t ro = (g * 16 + lrow) * AROWB + coff;
                uint32_t r[4];
                ldm_x4(r, sKh + ro);
                bh[2 * g][0] = r[0]; bh[2 * g][1] = r[2];
                bh[2 * g + 1][0] = r[1]; bh[2 * g + 1][1] = r[3];
                ldm_x4(r, sKl + ro);
                bl[2 * g][0] = r[0]; bl[2 * g][1] = r[2];
                bl[2 * g + 1][0] = r[1]; bl[2 * g + 1][1] = r[3];
            }
            #pragma unroll
            for (int nt = 0; nt < 8; nt++) {
                mma16816(sacc[nt], qh4, bh[nt]);
                mma16816(sacc[nt], qh4, bl[nt]);
                mma16816(sacc[nt], ql4, bh[nt]);
            }
        }

        // ---- online softmax (scores already in log2 units) ----
        float tm0 = -1e30f, tm1 = -1e30f;
        #pragma unroll
        for (int nt = 0; nt < 8; nt++) {
            tm0 = fmaxf(tm0, fmaxf(sacc[nt][0], sacc[nt][1]));
            tm1 = fmaxf(tm1, fmaxf(sacc[nt][2], sacc[nt][3]));
        }
        tm0 = fmaxf(tm0, __shfl_xor_sync(0xffffffffu, tm0, 1));
        tm0 = fmaxf(tm0, __shfl_xor_sync(0xffffffffu, tm0, 2));
        tm1 = fmaxf(tm1, __shfl_xor_sync(0xffffffffu, tm1, 1));
        tm1 = fmaxf(tm1, __shfl_xor_sync(0xffffffffu, tm1, 2));
        const float nm0 = fmaxf(m0, tm0), nm1 = fmaxf(m1, tm1);
        const float cr0 = ex2(m0 - nm0), cr1 = ex2(m1 - nm1);
        m0 = nm0; m1 = nm1;
        l0 *= cr0; l1 *= cr1;
        #pragma unroll
        for (int nd = 0; nd < 8; nd++) {
            oacc[nd][0] *= cr0; oacc[nd][1] *= cr0;
            oacc[nd][2] *= cr1; oacc[nd][3] *= cr1;
        }
        float rs0 = 0.f, rs1 = 0.f;
        #pragma unroll
        for (int nt = 0; nt < 8; nt++) {
            float p0 = ex2(sacc[nt][0] - m0), p1 = ex2(sacc[nt][1] - m0);
            float p2 = ex2(sacc[nt][2] - m1), p3 = ex2(sacc[nt][3] - m1);
            sacc[nt][0] = p0; sacc[nt][1] = p1; sacc[nt][2] = p2; sacc[nt][3] = p3;
            rs0 += p0 + p1; rs1 += p2 + p3;
        }
        rs0 += __shfl_xor_sync(0xffffffffu, rs0, 1);
        rs0 += __shfl_xor_sync(0xffffffffu, rs0, 2);
        rs1 += __shfl_xor_sync(0xffffffffu, rs1, 1);
        rs1 += __shfl_xor_sync(0xffffffffu, rs1, 2);
        l0 += rs0; l1 += rs1;

        // ---- O += P V (P split: trunc-hi + residual) ----
        #pragma unroll
        for (int kt = 0; kt < 4; kt++) {
            uint32_t ah[4], al[4];
            #pragma unroll
            for (int half = 0; half < 2; half++) {
                const float* sp = sacc[2 * kt + half];
                uint32_t u0 = __float_as_uint(sp[0]), u1 = __float_as_uint(sp[1]);
                uint32_t u2 = __float_as_uint(sp[2]), u3 = __float_as_uint(sp[3]);
                ah[half * 2 + 0] = prmt_hihi(u0, u1);
                ah[half * 2 + 1] = prmt_hihi(u2, u3);
                al[half * 2 + 0] = pack_bf16x2_rn(
                    sp[0] - __uint_as_float(u0 & 0xffff0000u),
                    sp[1] - __uint_as_float(u1 & 0xffff0000u));
                al[half * 2 + 1] = pack_bf16x2_rn(
                    sp[2] - __uint_as_float(u2 & 0xffff0000u),
                    sp[3] - __uint_as_float(u3 & 0xffff0000u));
            }
            uint32_t bvh[8][2], bvl[8][2];
            #pragma unroll
            for (int nd2 = 0; nd2 < 4; nd2++) {
                const uint32_t ro = (kt * 16 + lrow) * AROWB + nd2 * 32 + lcol;
                uint32_t r[4];
                ldm_x4_t(r, sVh + ro);
                bvh[2 * nd2][0] = r[0]; bvh[2 * nd2][1] = r[1];
                bvh[2 * nd2 + 1][0] = r[2]; bvh[2 * nd2 + 1][1] = r[3];
                ldm_x4_t(r, sVl + ro);
                bvl[2 * nd2][0] = r[0]; bvl[2 * nd2][1] = r[1];
                bvl[2 * nd2 + 1][0] = r[2]; bvl[2 * nd2 + 1][1] = r[3];
            }
            #pragma unroll
            for (int nd = 0; nd < 8; nd++) {
                mma16816(oacc[nd], ah, bvh[nd]);
                mma16816(oacc[nd], ah, bvl[nd]);
                mma16816(oacc[nd], al, bvh[nd]);
            }
        }

        __syncthreads();
        if (c + 2 < 32) {
            const uint32_t nb = sb + 2 * QTILEB + (c & 1) * KVBUF;
            const size_t j0 = (size_t)((c + 2) * 64) * 3072;
            att_load(nb + 0 * KTILEB, kh_b + j0, 2, t);
            att_load(nb + 1 * KTILEB, kl_b + j0, 2, t);
            att_load(nb + 2 * KTILEB, vh_b + j0, 2, t);
            att_load(nb + 3 * KTILEB, vl_b + j0, 2, t);
            CP_COMMIT();
        }
    }

    // ---- epilogue: normalize + split-write ----
    const float inv0 = 1.f / l0, inv1 = 1.f / l1;
    const int r0 = q0 + wid * 16 + (lane >> 2);
    #pragma unroll
    for (int nd = 0; nd < 8; nd++) {
        const int col = h * 64 + nd * 8 + (lane & 3) * 2;
        #pragma unroll
        for (int hrow = 0; hrow < 2; hrow++) {
            const float inv = hrow ? inv1 : inv0;
            const float v0 = oacc[nd][hrow * 2] * inv;
            const float v1 = oacc[nd][hrow * 2 + 1] * inv;
            __nv_bfloat162 hh = __float22bfloat162_rn(make_float2(v0, v1));
            __nv_bfloat162 ll = __float22bfloat162_rn(
                make_float2(v0 - __low2float(hh), v1 - __high2float(hh)));
            const size_t off = (rb + r0 + 8 * hrow) * 1024 + col;
            *(__nv_bfloat162*)(outhi + off) = hh;
            *(__nv_bfloat162*)(outlo + off) = ll;
        }
    }
}

// ------------------------- launch ------------------------------------------
extern "C" void kernel_launch(void* const* d_in, const int* in_sizes, int n_in,
                              void* d_out, int out_size)
{
    const float* x     = (const float*)d_in[0];
    const float* w_qkv = (const float*)d_in[1];
    const float* w_out = (const float*)d_in[2];
    const float* b_out = (const float*)d_in[3];
    float* out = (float*)d_out;

    __nv_bfloat16 *xhi, *xlo, *wqh, *wql, *woh, *wol, *qh, *ql, *ahi, *alo;
    cudaGetSymbolAddress((void**)&xhi, g_xhi);
    cudaGetSymbolAddress((void**)&xlo, g_xlo);
    cudaGetSymbolAddress((void**)&wqh, g_wqkvt_hi);
    cudaGetSymbolAddress((void**)&wql, g_wqkvt_lo);
    cudaGetSymbolAddress((void**)&woh, g_woutt_hi);
    cudaGetSymbolAddress((void**)&wol, g_woutt_lo);
    cudaGetSymbolAddress((void**)&qh, g_qkvhi);
    cudaGetSymbolAddress((void**)&ql, g_qkvlo);
    cudaGetSymbolAddress((void**)&ahi, g_atthi);
    cudaGetSymbolAddress((void**)&alo, g_attlo);

    cudaFuncSetAttribute(gemm_mma<0>, cudaFuncAttributeMaxDynamicSharedMemorySize,
                         SMEM_GEMM_BYTES);
    cudaFuncSetAttribute(gemm_mma<1>, cudaFuncAttributeMaxDynamicSharedMemorySize,
                         SMEM_GEMM_BYTES);
    cudaFuncSetAttribute(attn_mma, cudaFuncAttributeMaxDynamicSharedMemorySize,
                         SMEM_ATT_BYTES);

    // prep: splits + weight transposes (scale*log2e folded into q-cols)
    split_fp32<<<(8192 * 1024 / 4 + 255) / 256, 256>>>(x, xhi, xlo, 8192 * 1024 / 4);
    transpose_split<<<dim3(3072 / 32, 1024 / 32), dim3(32, 8)>>>(
        w_qkv, wqh, wql, 1024, 3072, 1024, ATT_SCALE * LOG2E);
    transpose_split<<<dim3(1024 / 32, 1024 / 32), dim3(32, 8)>>>(
        w_out, woh, wol, 1024, 1024, 0, 1.f);

    // stage 1: qkv = x @ w_qkv  (writes split hi/lo directly)
    gemm_mma<0><<<dim3(3072 / 128, 8192 / 128), 256, SMEM_GEMM_BYTES>>>(
        xhi, xlo, wqh, wql, nullptr, qh, ql, nullptr, 3072, 1024);

    // stage 2: flash attention (HMMA), writes split att
    attn_mma<<<dim3(2048 / 128, 64), 256, SMEM_ATT_BYTES>>>(qh, ql, ahi, alo);

    // stage 3: out = att @ w_out + b
    gemm_mma<1><<<dim3(1024 / 128, 8192 / 128), 256, SMEM_GEMM_BYTES>>>(
        ahi, alo, woh, wol, b_out, nullptr, nullptr, out, 1024, 1024);
}

// round 7
// speedup vs baseline: 3.7116x; 1.0014x over previous
#include <cuda_runtime.h>
#include <cuda_bf16.h>
#include <cstdint>

// ---------------------------------------------------------------------------
// Attention_71485435675049 — Round 7
// R6 + MMA issue-order fix: term-outer / accumulator-inner sweeps to break
// accumulator RAW chains (in-order issue stalls at HMMA latency, not rt).
// ---------------------------------------------------------------------------

#define ATT_SCALE 0.125f
#define LOG2E 1.4426950408889634f

// ------------------------- scratch (no allocs allowed) ----------------------
__device__ __nv_bfloat16 g_xhi[8192 * 1024];
__device__ __nv_bfloat16 g_xlo[8192 * 1024];
__device__ __nv_bfloat16 g_wqkvt_hi[3072 * 1024];   // [N,K] transposed
__device__ __nv_bfloat16 g_wqkvt_lo[3072 * 1024];
__device__ __nv_bfloat16 g_woutt_hi[1024 * 1024];
__device__ __nv_bfloat16 g_woutt_lo[1024 * 1024];
__device__ __nv_bfloat16 g_qkvhi[8192 * 3072];
__device__ __nv_bfloat16 g_qkvlo[8192 * 3072];
__device__ __nv_bfloat16 g_atthi[8192 * 1024];
__device__ __nv_bfloat16 g_attlo[8192 * 1024];

// ------------------------- PTX helpers -------------------------------------
__device__ __forceinline__ uint32_t smem_u32(const void* p) {
    uint32_t a;
    asm("{ .reg .u64 t; cvta.to.shared.u64 t, %1; cvt.u32.u64 %0, t; }"
        : "=r"(a) : "l"(p));
    return a;
}

__device__ __forceinline__ void cp_async16(uint32_t dst, const void* src) {
    asm volatile("cp.async.cg.shared.global [%0], [%1], 16;\n"
                 :: "r"(dst), "l"(src));
}
#define CP_COMMIT() asm volatile("cp.async.commit_group;\n" ::: "memory")
#define CP_WAIT(n)  asm volatile("cp.async.wait_group %0;\n" :: "n"(n) : "memory")

__device__ __forceinline__ void ldm_x4(uint32_t r[4], uint32_t addr) {
    asm volatile("ldmatrix.sync.aligned.m8n8.x4.shared.b16 {%0,%1,%2,%3}, [%4];"
                 : "=r"(r[0]), "=r"(r[1]), "=r"(r[2]), "=r"(r[3]) : "r"(addr));
}
__device__ __forceinline__ void ldm_x4_t(uint32_t r[4], uint32_t addr) {
    asm volatile("ldmatrix.sync.aligned.m8n8.x4.trans.shared.b16 {%0,%1,%2,%3}, [%4];"
                 : "=r"(r[0]), "=r"(r[1]), "=r"(r[2]), "=r"(r[3]) : "r"(addr));
}

__device__ __forceinline__ void mma16816(float c[4], const uint32_t a[4],
                                         const uint32_t b[2]) {
    asm volatile(
        "mma.sync.aligned.m16n8k16.row.col.f32.bf16.bf16.f32 "
        "{%0,%1,%2,%3}, {%4,%5,%6,%7}, {%8,%9}, {%0,%1,%2,%3};"
        : "+f"(c[0]), "+f"(c[1]), "+f"(c[2]), "+f"(c[3])
        : "r"(a[0]), "r"(a[1]), "r"(a[2]), "r"(a[3]), "r"(b[0]), "r"(b[1]));
}

__device__ __forceinline__ float ex2(float x) {
    float r; asm("ex2.approx.f32 %0, %1;" : "=f"(r) : "f"(x)); return r;
}
__device__ __forceinline__ uint32_t prmt_hihi(uint32_t a, uint32_t b) {
    uint32_t d;
    asm("prmt.b32 %0, %1, %2, 0x7632;" : "=r"(d) : "r"(a), "r"(b));
    return d;
}
__device__ __forceinline__ uint32_t pack_bf16x2_rn(float lo, float hi) {
    uint32_t d;
    asm("cvt.rn.bf16x2.f32 %0, %1, %2;" : "=r"(d) : "f"(hi), "f"(lo));
    return d;
}

// ------------------------- conversion kernels ------------------------------
__global__ void split_fp32(const float* __restrict__ src,
                           __nv_bfloat16* __restrict__ hi,
                           __nv_bfloat16* __restrict__ lo, int n4) {
    int i = blockIdx.x * blockDim.x + threadIdx.x;
    if (i >= n4) return;
    float4 v = ((const float4*)src)[i];
    __nv_bfloat16 h0 = __float2bfloat16(v.x), h1 = __float2bfloat16(v.y);
    __nv_bfloat16 h2 = __float2bfloat16(v.z), h3 = __float2bfloat16(v.w);
    hi[i * 4 + 0] = h0; hi[i * 4 + 1] = h1; hi[i * 4 + 2] = h2; hi[i * 4 + 3] = h3;
    lo[i * 4 + 0] = __float2bfloat16(v.x - __bfloat162float(h0));
    lo[i * 4 + 1] = __float2bfloat16(v.y - __bfloat162float(h1));
    lo[i * 4 + 2] = __float2bfloat16(v.z - __bfloat162float(h2));
    lo[i * 4 + 3] = __float2bfloat16(v.w - __bfloat162float(h3));
}

// src[K,N] fp32 -> out[N,K] bf16 hi/lo; cols < scale_cols scaled by `scale`
__global__ void transpose_split(const float* __restrict__ src,
                                __nv_bfloat16* __restrict__ hi,
                                __nv_bfloat16* __restrict__ lo,
                                int K, int N, int scale_cols, float scale) {
    __shared__ float tile[32][33];
    const int n0 = blockIdx.x * 32, k0 = blockIdx.y * 32;
    const int tx = threadIdx.x, ty = threadIdx.y;
    #pragma unroll
    for (int j = 0; j < 4; j++) {
        int r = ty + j * 8;
        float v = src[(size_t)(k0 + r) * N + n0 + tx];
        if (n0 + tx < scale_cols) v *= scale;
        tile[r][tx] = v;
    }
    __syncthreads();
    #pragma unroll
    for (int j = 0; j < 4; j++) {
        int b = ty + j * 8;
        float v = tile[tx][b];
        __nv_bfloat16 h = __float2bfloat16(v);
        size_t o = (size_t)(n0 + b) * K + k0 + tx;
        hi[o] = h;
        lo[o] = __float2bfloat16(v - __bfloat162float(h));
    }
}

// ------------------------- HMMA GEMM ---------------------------------------
constexpr int ROWB = 80;
constexpr int TILEB = 128 * ROWB;
constexpr int BUFB = 4 * TILEB;
constexpr int SMEM_GEMM_BYTES = 2 * BUFB;     // 81920

__device__ __forceinline__ void load_tile_p(uint32_t dst, const __nv_bfloat16* src,
                                            int row0, int k0, int K, int t) {
    const char* sp = (const char*)(src + (size_t)row0 * K + k0);
    const size_t rs = (size_t)K * 2;
    #pragma unroll
    for (int i = 0; i < 2; i++) {
        int s = i * 256 + t;
        int row = s >> 2, seg = (s & 3) * 16;
        cp_async16(dst + row * ROWB + seg, sp + (size_t)row * rs + seg);
    }
}

template <int MODE>
__global__ __launch_bounds__(256) void gemm_mma(
    const __nv_bfloat16* __restrict__ Ahi, const __nv_bfloat16* __restrict__ Alo,
    const __nv_bfloat16* __restrict__ Bhi, const __nv_bfloat16* __restrict__ Blo,
    const float* __restrict__ bias,
    __nv_bfloat16* __restrict__ Chi, __nv_bfloat16* __restrict__ Clo,
    float* __restrict__ Cf, int N, int K)
{
    extern __shared__ char smem[];
    const uint32_t sb = smem_u32(smem);
    const int t = threadIdx.x, wid = t >> 5, lane = t & 31;
    const int warp_m = wid & 3, warp_n = wid >> 2;

    const int rowA = blockIdx.y * 128, rowB = blockIdx.x * 128;
    const int nch = K / 32;

    float acc[2][8][4];
    #pragma unroll
    for (int mt = 0; mt < 2; mt++)
        #pragma unroll
        for (int nt = 0; nt < 8; nt++)
            #pragma unroll
            for (int j = 0; j < 4; j++) acc[mt][nt][j] = 0.f;

    #pragma unroll
    for (int c = 0; c < 2; c++) {
        uint32_t bb = sb + (c & 1) * BUFB;
        load_tile_p(bb + 0 * TILEB, Ahi, rowA, c * 32, K, t);
        load_tile_p(bb + 1 * TILEB, Alo, rowA, c * 32, K, t);
        load_tile_p(bb + 2 * TILEB, Bhi, rowB, c * 32, K, t);
        load_tile_p(bb + 3 * TILEB, Blo, rowB, c * 32, K, t);
        CP_COMMIT();
    }

    const int lrow = lane & 15;
    const uint32_t lcol = (lane >> 4) << 4;

    for (int c = 0; c < nch; c++) {
        if (c == nch - 1) { CP_WAIT(0); } else { CP_WAIT(1); }
        __syncthreads();
        const uint32_t bb = sb + (c & 1) * BUFB;
        const uint32_t sAh = bb, sAl = bb + TILEB;
        const uint32_t sBh = bb + 2 * TILEB, sBl = bb + 3 * TILEB;

        #pragma unroll
        for (int kk = 0; kk < 2; kk++) {
            const uint32_t coff = kk * 32 + lcol;
            uint32_t ah[2][4], al[2][4];
            #pragma unroll
            for (int mt = 0; mt < 2; mt++) {
                const uint32_t ro = (warp_m * 32 + mt * 16 + lrow) * ROWB + coff;
                ldm_x4(ah[mt], sAh + ro);
                ldm_x4(al[mt], sAl + ro);
            }
            uint32_t bh[8][2], bl[8][2];
            #pragma unroll
            for (int g = 0; g < 4; g++) {
                const uint32_t ro = (warp_n * 64 + g * 16 + lrow) * ROWB + coff;
                uint32_t r[4];
                ldm_x4(r, sBh + ro);
                bh[2 * g][0] = r[0]; bh[2 * g][1] = r[2];
                bh[2 * g + 1][0] = r[1]; bh[2 * g + 1][1] = r[3];
                ldm_x4(r, sBl + ro);
                bl[2 * g][0] = r[0]; bl[2 * g][1] = r[2];
                bl[2 * g + 1][0] = r[1]; bl[2 * g + 1][1] = r[3];
            }
            // term-outer / accumulator-inner: adjacent MMAs hit distinct accs
            // (per-acc term order unchanged -> bitwise-identical result)
            #pragma unroll
            for (int mt = 0; mt < 2; mt++)
                #pragma unroll
                for (int nt = 0; nt < 8; nt++)
                    mma16816(acc[mt][nt], ah[mt], bh[nt]);
            #pragma unroll
            for (int mt = 0; mt < 2; mt++)
                #pragma unroll
                for (int nt = 0; nt < 8; nt++)
                    mma16816(acc[mt][nt], ah[mt], bl[nt]);
            #pragma unroll
            for (int mt = 0; mt < 2; mt++)
                #pragma unroll
                for (int nt = 0; nt < 8; nt++)
                    mma16816(acc[mt][nt], al[mt], bh[nt]);
        }
        __syncthreads();
        if (c + 2 < nch) {
            uint32_t nb = sb + (c & 1) * BUFB;
            load_tile_p(nb + 0 * TILEB, Ahi, rowA, (c + 2) * 32, K, t);
            load_tile_p(nb + 1 * TILEB, Alo, rowA, (c + 2) * 32, K, t);
            load_tile_p(nb + 2 * TILEB, Bhi, rowB, (c + 2) * 32, K, t);
            load_tile_p(nb + 3 * TILEB, Blo, rowB, (c + 2) * 32, K, t);
            CP_COMMIT();
        }
    }

    // epilogue
    #pragma unroll
    for (int mt = 0; mt < 2; mt++) {
        const int r0 = blockIdx.y * 128 + warp_m * 32 + mt * 16 + (lane >> 2);
        #pragma unroll
        for (int nt = 0; nt < 8; nt++) {
            const int col = blockIdx.x * 128 + warp_n * 64 + nt * 8 + (lane & 3) * 2;
            if (MODE == 1) {
                const float2 b2 = *(const float2*)(bias + col);
                *(float2*)(Cf + (size_t)r0 * N + col) =
                    make_float2(acc[mt][nt][0] + b2.x, acc[mt][nt][1] + b2.y);
                *(float2*)(Cf + (size_t)(r0 + 8) * N + col) =
                    make_float2(acc[mt][nt][2] + b2.x, acc[mt][nt][3] + b2.y);
            } else {
                #pragma unroll
                for (int hrow = 0; hrow < 2; hrow++) {
                    const float v0 = acc[mt][nt][hrow * 2];
                    const float v1 = acc[mt][nt][hrow * 2 + 1];
                    __nv_bfloat162 h = __float22bfloat162_rn(make_float2(v0, v1));
                    __nv_bfloat162 l = __float22bfloat162_rn(
                        make_float2(v0 - __low2float(h), v1 - __high2float(h)));
                    const size_t off = (size_t)(r0 + 8 * hrow) * N + col;
                    *(__nv_bfloat162*)(Chi + off) = h;
                    *(__nv_bfloat162*)(Clo + off) = l;
                }
            }
        }
    }
}

// ------------------------- HMMA flash attention ----------------------------
constexpr int AROWB = 144;
constexpr int QTILEB = 128 * AROWB;            // 18432
constexpr int KTILEB = 64 * AROWB;             // 9216
constexpr int KVBUF = 4 * KTILEB;              // 36864
constexpr int SMEM_ATT_BYTES = 2 * QTILEB + 2 * KVBUF;  // 110592

__device__ __forceinline__ void att_load(uint32_t dst, const __nv_bfloat16* src,
                                         int rows256, int t) {
    #pragma unroll
    for (int i = 0; i < 4; i++) {
        if (i >= rows256) break;
        int s = i * 256 + t;
        int r = s >> 3, seg = (s & 7) * 16;
        cp_async16(dst + r * AROWB + seg, (const char*)src + (size_t)r * 6144 + seg);
    }
}

__global__ __launch_bounds__(256) void attn_mma(
    const __nv_bfloat16* __restrict__ qkvh, const __nv_bfloat16* __restrict__ qkvl,
    __nv_bfloat16* __restrict__ outhi, __nv_bfloat16* __restrict__ outlo)
{
    extern __shared__ char smem[];
    const uint32_t sb = smem_u32(smem);
    const int t = threadIdx.x, wid = t >> 5, lane = t & 31;
    const int bh_ = blockIdx.y, b = bh_ >> 4, h = bh_ & 15;
    const int q0 = blockIdx.x * 128;
    const size_t rb = (size_t)b * 2048;

    const uint32_t QH = sb, QL = sb + QTILEB;
    const __nv_bfloat16* kh_b = qkvh + rb * 3072 + 1024 + h * 64;
    const __nv_bfloat16* kl_b = qkvl + rb * 3072 + 1024 + h * 64;
    const __nv_bfloat16* vh_b = qkvh + rb * 3072 + 2048 + h * 64;
    const __nv_bfloat16* vl_b = qkvl + rb * 3072 + 2048 + h * 64;

    att_load(QH, qkvh + (rb + q0) * 3072 + h * 64, 4, t);
    att_load(QL, qkvl + (rb + q0) * 3072 + h * 64, 4, t);
    #pragma unroll
    for (int c = 0; c < 2; c++) {
        const uint32_t kb = sb + 2 * QTILEB + c * KVBUF;
        att_load(kb + 0 * KTILEB, kh_b + (size_t)(c * 64) * 3072, 2, t);
        att_load(kb + 1 * KTILEB, kl_b + (size_t)(c * 64) * 3072, 2, t);
        att_load(kb + 2 * KTILEB, vh_b + (size_t)(c * 64) * 3072, 2, t);
        att_load(kb + 3 * KTILEB, vl_b + (size_t)(c * 64) * 3072, 2, t);
        CP_COMMIT();
    }

    float oacc[8][4];
    #pragma unroll
    for (int nd = 0; nd < 8; nd++)
        #pragma unroll
        for (int j = 0; j < 4; j++) oacc[nd][j] = 0.f;
    float m0 = -1e30f, m1 = -1e30f, l0 = 0.f, l1 = 0.f;

    const int lrow = lane & 15;
    const uint32_t lcol = (lane >> 4) << 4;

    for (int c = 0; c < 32; c++) {
        if (c == 31) { CP_WAIT(0); } else { CP_WAIT(1); }
        __syncthreads();
        const uint32_t kb = sb + 2 * QTILEB + (c & 1) * KVBUF;
        const uint32_t sKh = kb, sKl = kb + KTILEB;
        const uint32_t sVh = kb + 2 * KTILEB, sVl = kb + 3 * KTILEB;

        // ---- S = Q K^T (3-term, term-outer sweeps) ----
        float sacc[8][4];
        #pragma unroll
        for (int nt = 0; nt < 8; nt++)
            #pragma unroll
            for (int j = 0; j < 4; j++) sacc[nt][j] = 0.f;

        #pragma unroll
        for (int kt = 0; kt < 4; kt++) {
            const uint32_t coff = kt * 32 + lcol;
            uint32_t qh4[4], ql4[4];
            const uint32_t qro = (wid * 16 + lrow) * AROWB + coff;
            ldm_x4(qh4, QH + qro);
            ldm_x4(ql4, QL + qro);
            uint32_t bh[8][2], bl[8][2];
            #pragma unroll
            for (int g = 0; g < 4; g++) {
                const uint32_t ro = (g * 16 + lrow) * AROWB + coff;
                uint32_t r[4];
                ldm_x4(r, sKh + ro);
                bh[2 * g][0] = r[0]; bh[2 * g][1] = r[2];
                bh[2 * g + 1][0] = r[1]; bh[2 * g + 1][1] = r[3];
                ldm_x4(r, sKl + ro);
                bl[2 * g][0] = r[0]; bl[2 * g][1] = r[2];
                bl[2 * g + 1][0] = r[1]; bl[2 * g + 1][1] = r[3];
            }
            #pragma unroll
            for (int nt = 0; nt < 8; nt++)
                mma16816(sacc[nt], qh4, bh[nt]);
            #pragma unroll
            for (int nt = 0; nt < 8; nt++)
                mma16816(sacc[nt], qh4, bl[nt]);
            #pragma unroll
            for (int nt = 0; nt < 8; nt++)
                mma16816(sacc[nt], ql4, bh[nt]);
        }

        // ---- online softmax (log2 units) ----
        float tm0 = -1e30f, tm1 = -1e30f;
        #pragma unroll
        for (int nt = 0; nt < 8; nt++) {
            tm0 = fmaxf(tm0, fmaxf(sacc[nt][0], sacc[nt][1]));
            tm1 = fmaxf(tm1, fmaxf(sacc[nt][2], sacc[nt][3]));
        }
        tm0 = fmaxf(tm0, __shfl_xor_sync(0xffffffffu, tm0, 1));
        tm0 = fmaxf(tm0, __shfl_xor_sync(0xffffffffu, tm0, 2));
        tm1 = fmaxf(tm1, __shfl_xor_sync(0xffffffffu, tm1, 1));
        tm1 = fmaxf(tm1, __shfl_xor_sync(0xffffffffu, tm1, 2));
        const float nm0 = fmaxf(m0, tm0), nm1 = fmaxf(m1, tm1);
        const float cr0 = ex2(m0 - nm0), cr1 = ex2(m1 - nm1);
        m0 = nm0; m1 = nm1;
        l0 *= cr0; l1 *= cr1;
        #pragma unroll
        for (int nd = 0; nd < 8; nd++) {
            oacc[nd][0] *= cr0; oacc[nd][1] *= cr0;
            oacc[nd][2] *= cr1; oacc[nd][3] *= cr1;
        }
        float rs0 = 0.f, rs1 = 0.f;
        #pragma unroll
        for (int nt = 0; nt < 8; nt++) {
            float p0 = ex2(sacc[nt][0] - m0), p1 = ex2(sacc[nt][1] - m0);
            float p2 = ex2(sacc[nt][2] - m1), p3 = ex2(sacc[nt][3] - m1);
            sacc[nt][0] = p0; sacc[nt][1] = p1; sacc[nt][2] = p2; sacc[nt][3] = p3;
            rs0 += p0 + p1; rs1 += p2 + p3;
        }
        rs0 += __shfl_xor_sync(0xffffffffu, rs0, 1);
        rs0 += __shfl_xor_sync(0xffffffffu, rs0, 2);
        rs1 += __shfl_xor_sync(0xffffffffu, rs1, 1);
        rs1 += __shfl_xor_sync(0xffffffffu, rs1, 2);
        l0 += rs0; l1 += rs1;

        // ---- O += P V (P split; term-outer sweeps) ----
        #pragma unroll
        for (int kt = 0; kt < 4; kt++) {
            uint32_t ah[4], al[4];
            #pragma unroll
            for (int half = 0; half < 2; half++) {
                const float* sp = sacc[2 * kt + half];
                uint32_t u0 = __float_as_uint(sp[0]), u1 = __float_as_uint(sp[1]);
                uint32_t u2 = __float_as_uint(sp[2]), u3 = __float_as_uint(sp[3]);
                ah[half * 2 + 0] = prmt_hihi(u0, u1);
                ah[half * 2 + 1] = prmt_hihi(u2, u3);
                al[half * 2 + 0] = pack_bf16x2_rn(
                    sp[0] - __uint_as_float(u0 & 0xffff0000u),
                    sp[1] - __uint_as_float(u1 & 0xffff0000u));
                al[half * 2 + 1] = pack_bf16x2_rn(
                    sp[2] - __uint_as_float(u2 & 0xffff0000u),
                    sp[3] - __uint_as_float(u3 & 0xffff0000u));
            }
            uint32_t bvh[8][2], bvl[8][2];
            #pragma unroll
            for (int nd2 = 0; nd2 < 4; nd2++) {
                const uint32_t ro = (kt * 16 + lrow) * AROWB + nd2 * 32 + lcol;
                uint32_t r[4];
                ldm_x4_t(r, sVh + ro);
                bvh[2 * nd2][0] = r[0]; bvh[2 * nd2][1] = r[1];
                bvh[2 * nd2 + 1][0] = r[2]; bvh[2 * nd2 + 1][1] = r[3];
                ldm_x4_t(r, sVl + ro);
                bvl[2 * nd2][0] = r[0]; bvl[2 * nd2][1] = r[1];
                bvl[2 * nd2 + 1][0] = r[2]; bvl[2 * nd2 + 1][1] = r[3];
            }
            #pragma unroll
            for (int nd = 0; nd < 8; nd++)
                mma16816(oacc[nd], ah, bvh[nd]);
            #pragma unroll
            for (int nd = 0; nd < 8; nd++)
                mma16816(oacc[nd], ah, bvl[nd]);
            #pragma unroll
            for (int nd = 0; nd < 8; nd++)
                mma16816(oacc[nd], al, bvh[nd]);
        }

        __syncthreads();
        if (c + 2 < 32) {
            const uint32_t nb = sb + 2 * QTILEB + (c & 1) * KVBUF;
            const size_t j0 = (size_t)((c + 2) * 64) * 3072;
            att_load(nb + 0 * KTILEB, kh_b + j0, 2, t);
            att_load(nb + 1 * KTILEB, kl_b + j0, 2, t);
            att_load(nb + 2 * KTILEB, vh_b + j0, 2, t);
            att_load(nb + 3 * KTILEB, vl_b + j0, 2, t);
            CP_COMMIT();
        }
    }

    // ---- epilogue ----
    const float inv0 = 1.f / l0, inv1 = 1.f / l1;
    const int r0 = q0 + wid * 16 + (lane >> 2);
    #pragma unroll
    for (int nd = 0; nd < 8; nd++) {
        const int col = h * 64 + nd * 8 + (lane & 3) * 2;
        #pragma unroll
        for (int hrow = 0; hrow < 2; hrow++) {
            const float inv = hrow ? inv1 : inv0;
            const float v0 = oacc[nd][hrow * 2] * inv;
            const float v1 = oacc[nd][hrow * 2 + 1] * inv;
            __nv_bfloat162 hh = __float22bfloat162_rn(make_float2(v0, v1));
            __nv_bfloat162 ll = __float22bfloat162_rn(
                make_float2(v0 - __low2float(hh), v1 - __high2float(hh)));
            const size_t off = (rb + r0 + 8 * hrow) * 1024 + col;
            *(__nv_bfloat162*)(outhi + off) = hh;
            *(__nv_bfloat162*)(outlo + off) = ll;
        }
    }
}

// ------------------------- launch ------------------------------------------
extern "C" void kernel_launch(void* const* d_in, const int* in_sizes, int n_in,
                              void* d_out, int out_size)
{
    const float* x     = (const float*)d_in[0];
    const float* w_qkv = (const float*)d_in[1];
    const float* w_out = (const float*)d_in[2];
    const float* b_out = (const float*)d_in[3];
    float* out = (float*)d_out;

    __nv_bfloat16 *xhi, *xlo, *wqh, *wql, *woh, *wol, *qh, *ql, *ahi, *alo;
    cudaGetSymbolAddress((void**)&xhi, g_xhi);
    cudaGetSymbolAddress((void**)&xlo, g_xlo);
    cudaGetSymbolAddress((void**)&wqh, g_wqkvt_hi);
    cudaGetSymbolAddress((void**)&wql, g_wqkvt_lo);
    cudaGetSymbolAddress((void**)&woh, g_woutt_hi);
    cudaGetSymbolAddress((void**)&wol, g_woutt_lo);
    cudaGetSymbolAddress((void**)&qh, g_qkvhi);
    cudaGetSymbolAddress((void**)&ql, g_qkvlo);
    cudaGetSymbolAddress((void**)&ahi, g_atthi);
    cudaGetSymbolAddress((void**)&alo, g_attlo);

    cudaFuncSetAttribute(gemm_mma<0>, cudaFuncAttributeMaxDynamicSharedMemorySize,
                         SMEM_GEMM_BYTES);
    cudaFuncSetAttribute(gemm_mma<1>, cudaFuncAttributeMaxDynamicSharedMemorySize,
                         SMEM_GEMM_BYTES);
    cudaFuncSetAttribute(attn_mma, cudaFuncAttributeMaxDynamicSharedMemorySize,
                         SMEM_ATT_BYTES);

    split_fp32<<<(8192 * 1024 / 4 + 255) / 256, 256>>>(x, xhi, xlo, 8192 * 1024 / 4);
    transpose_split<<<dim3(3072 / 32, 1024 / 32), dim3(32, 8)>>>(
        w_qkv, wqh, wql, 1024, 3072, 1024, ATT_SCALE * LOG2E);
    transpose_split<<<dim3(1024 / 32, 1024 / 32), dim3(32, 8)>>>(
        w_out, woh, wol, 1024, 1024, 0, 1.f);

    gemm_mma<0><<<dim3(3072 / 128, 8192 / 128), 256, SMEM_GEMM_BYTES>>>(
        xhi, xlo, wqh, wql, nullptr, qh, ql, nullptr, 3072, 1024);

    attn_mma<<<dim3(2048 / 128, 64), 256, SMEM_ATT_BYTES>>>(qh, ql, ahi, alo);

    gemm_mma<1><<<dim3(1024 / 128, 8192 / 128), 256, SMEM_GEMM_BYTES>>>(
        ahi, alo, woh, wol, b_out, nullptr, nullptr, out, 1024, 1024);
}

// round 8
// speedup vs baseline: 4.9901x; 1.3445x over previous
#include <cuda_runtime.h>
#include <cuda_bf16.h>
#include <cuda_fp16.h>
#include <cstdint>

// ---------------------------------------------------------------------------
// Attention_71485435675049 — Round 8
// gemm0/gemm1: bf16 hi/lo 3-term HMMA (validated, rel_err 2e-5 backbone).
// attention:   fp16 single-term HMMA (3x fewer MMAs, half smem traffic).
// gemm0 writes fp16 qkv directly; attention writes split bf16 for gemm1.
// ---------------------------------------------------------------------------

#define ATT_SCALE 0.125f
#define LOG2E 1.4426950408889634f

// ------------------------- scratch (no allocs allowed) ----------------------
__device__ __nv_bfloat16 g_xhi[8192 * 1024];
__device__ __nv_bfloat16 g_xlo[8192 * 1024];
__device__ __nv_bfloat16 g_wqkvt_hi[3072 * 1024];   // [N,K] transposed
__device__ __nv_bfloat16 g_wqkvt_lo[3072 * 1024];
__device__ __nv_bfloat16 g_woutt_hi[1024 * 1024];
__device__ __nv_bfloat16 g_woutt_lo[1024 * 1024];
__device__ __half        g_qkv16[8192 * 3072];
__device__ __nv_bfloat16 g_atthi[8192 * 1024];
__device__ __nv_bfloat16 g_attlo[8192 * 1024];

// ------------------------- PTX helpers -------------------------------------
__device__ __forceinline__ uint32_t smem_u32(const void* p) {
    uint32_t a;
    asm("{ .reg .u64 t; cvta.to.shared.u64 t, %1; cvt.u32.u64 %0, t; }"
        : "=r"(a) : "l"(p));
    return a;
}

__device__ __forceinline__ void cp_async16(uint32_t dst, const void* src) {
    asm volatile("cp.async.cg.shared.global [%0], [%1], 16;\n"
                 :: "r"(dst), "l"(src));
}
#define CP_COMMIT() asm volatile("cp.async.commit_group;\n" ::: "memory")
#define CP_WAIT(n)  asm volatile("cp.async.wait_group %0;\n" :: "n"(n) : "memory")

__device__ __forceinline__ void ldm_x4(uint32_t r[4], uint32_t addr) {
    asm volatile("ldmatrix.sync.aligned.m8n8.x4.shared.b16 {%0,%1,%2,%3}, [%4];"
                 : "=r"(r[0]), "=r"(r[1]), "=r"(r[2]), "=r"(r[3]) : "r"(addr));
}
__device__ __forceinline__ void ldm_x4_t(uint32_t r[4], uint32_t addr) {
    asm volatile("ldmatrix.sync.aligned.m8n8.x4.trans.shared.b16 {%0,%1,%2,%3}, [%4];"
                 : "=r"(r[0]), "=r"(r[1]), "=r"(r[2]), "=r"(r[3]) : "r"(addr));
}

__device__ __forceinline__ void mma16816(float c[4], const uint32_t a[4],
                                         const uint32_t b[2]) {
    asm volatile(
        "mma.sync.aligned.m16n8k16.row.col.f32.bf16.bf16.f32 "
        "{%0,%1,%2,%3}, {%4,%5,%6,%7}, {%8,%9}, {%0,%1,%2,%3};"
        : "+f"(c[0]), "+f"(c[1]), "+f"(c[2]), "+f"(c[3])
        : "r"(a[0]), "r"(a[1]), "r"(a[2]), "r"(a[3]), "r"(b[0]), "r"(b[1]));
}
__device__ __forceinline__ void mma16816h(float c[4], const uint32_t a[4],
                                          const uint32_t b[2]) {
    asm volatile(
        "mma.sync.aligned.m16n8k16.row.col.f32.f16.f16.f32 "
        "{%0,%1,%2,%3}, {%4,%5,%6,%7}, {%8,%9}, {%0,%1,%2,%3};"
        : "+f"(c[0]), "+f"(c[1]), "+f"(c[2]), "+f"(c[3])
        : "r"(a[0]), "r"(a[1]), "r"(a[2]), "r"(a[3]), "r"(b[0]), "r"(b[1]));
}

__device__ __forceinline__ float ex2(float x) {
    float r; asm("ex2.approx.f32 %0, %1;" : "=f"(r) : "f"(x)); return r;
}
__device__ __forceinline__ uint32_t pack_f16x2(float lo, float hi) {
    uint32_t d;
    asm("cvt.rn.f16x2.f32 %0, %1, %2;" : "=r"(d) : "f"(hi), "f"(lo));
    return d;
}

// ------------------------- conversion kernels ------------------------------
__global__ void split_fp32(const float* __restrict__ src,
                           __nv_bfloat16* __restrict__ hi,
                           __nv_bfloat16* __restrict__ lo, int n4) {
    int i = blockIdx.x * blockDim.x + threadIdx.x;
    if (i >= n4) return;
    float4 v = ((const float4*)src)[i];
    __nv_bfloat16 h0 = __float2bfloat16(v.x), h1 = __float2bfloat16(v.y);
    __nv_bfloat16 h2 = __float2bfloat16(v.z), h3 = __float2bfloat16(v.w);
    hi[i * 4 + 0] = h0; hi[i * 4 + 1] = h1; hi[i * 4 + 2] = h2; hi[i * 4 + 3] = h3;
    lo[i * 4 + 0] = __float2bfloat16(v.x - __bfloat162float(h0));
    lo[i * 4 + 1] = __float2bfloat16(v.y - __bfloat162float(h1));
    lo[i * 4 + 2] = __float2bfloat16(v.z - __bfloat162float(h2));
    lo[i * 4 + 3] = __float2bfloat16(v.w - __bfloat162float(h3));
}

// src[K,N] fp32 -> out[N,K] bf16 hi/lo; cols < scale_cols scaled by `scale`
__global__ void transpose_split(const float* __restrict__ src,
                                __nv_bfloat16* __restrict__ hi,
                                __nv_bfloat16* __restrict__ lo,
                                int K, int N, int scale_cols, float scale) {
    __shared__ float tile[32][33];
    const int n0 = blockIdx.x * 32, k0 = blockIdx.y * 32;
    const int tx = threadIdx.x, ty = threadIdx.y;
    #pragma unroll
    for (int j = 0; j < 4; j++) {
        int r = ty + j * 8;
        float v = src[(size_t)(k0 + r) * N + n0 + tx];
        if (n0 + tx < scale_cols) v *= scale;
        tile[r][tx] = v;
    }
    __syncthreads();
    #pragma unroll
    for (int j = 0; j < 4; j++) {
        int b = ty + j * 8;
        float v = tile[tx][b];
        __nv_bfloat16 h = __float2bfloat16(v);
        size_t o = (size_t)(n0 + b) * K + k0 + tx;
        hi[o] = h;
        lo[o] = __float2bfloat16(v - __bfloat162float(h));
    }
}

// ------------------------- HMMA GEMM (bf16 3-term) --------------------------
constexpr int ROWB = 80;
constexpr int TILEB = 128 * ROWB;
constexpr int BUFB = 4 * TILEB;
constexpr int SMEM_GEMM_BYTES = 2 * BUFB;     // 81920

__device__ __forceinline__ void load_tile_p(uint32_t dst, const __nv_bfloat16* src,
                                            int row0, int k0, int K, int t) {
    const char* sp = (const char*)(src + (size_t)row0 * K + k0);
    const size_t rs = (size_t)K * 2;
    #pragma unroll
    for (int i = 0; i < 2; i++) {
        int s = i * 256 + t;
        int row = s >> 2, seg = (s & 3) * 16;
        cp_async16(dst + row * ROWB + seg, sp + (size_t)row * rs + seg);
    }
}

// MODE 0: write fp16 (qkv). MODE 1: write fp32 + bias.
template <int MODE>
__global__ __launch_bounds__(256) void gemm_mma(
    const __nv_bfloat16* __restrict__ Ahi, const __nv_bfloat16* __restrict__ Alo,
    const __nv_bfloat16* __restrict__ Bhi, const __nv_bfloat16* __restrict__ Blo,
    const float* __restrict__ bias,
    __half* __restrict__ Ch, float* __restrict__ Cf, int N, int K)
{
    extern __shared__ char smem[];
    const uint32_t sb = smem_u32(smem);
    const int t = threadIdx.x, wid = t >> 5, lane = t & 31;
    const int warp_m = wid & 3, warp_n = wid >> 2;

    const int rowA = blockIdx.y * 128, rowB = blockIdx.x * 128;
    const int nch = K / 32;

    float acc[2][8][4];
    #pragma unroll
    for (int mt = 0; mt < 2; mt++)
        #pragma unroll
        for (int nt = 0; nt < 8; nt++)
            #pragma unroll
            for (int j = 0; j < 4; j++) acc[mt][nt][j] = 0.f;

    #pragma unroll
    for (int c = 0; c < 2; c++) {
        uint32_t bb = sb + (c & 1) * BUFB;
        load_tile_p(bb + 0 * TILEB, Ahi, rowA, c * 32, K, t);
        load_tile_p(bb + 1 * TILEB, Alo, rowA, c * 32, K, t);
        load_tile_p(bb + 2 * TILEB, Bhi, rowB, c * 32, K, t);
        load_tile_p(bb + 3 * TILEB, Blo, rowB, c * 32, K, t);
        CP_COMMIT();
    }

    const int lrow = lane & 15;
    const uint32_t lcol = (lane >> 4) << 4;

    for (int c = 0; c < nch; c++) {
        if (c == nch - 1) { CP_WAIT(0); } else { CP_WAIT(1); }
        __syncthreads();
        const uint32_t bb = sb + (c & 1) * BUFB;
        const uint32_t sAh = bb, sAl = bb + TILEB;
        const uint32_t sBh = bb + 2 * TILEB, sBl = bb + 3 * TILEB;

        #pragma unroll
        for (int kk = 0; kk < 2; kk++) {
            const uint32_t coff = kk * 32 + lcol;
            uint32_t ah[2][4], al[2][4];
            #pragma unroll
            for (int mt = 0; mt < 2; mt++) {
                const uint32_t ro = (warp_m * 32 + mt * 16 + lrow) * ROWB + coff;
                ldm_x4(ah[mt], sAh + ro);
                ldm_x4(al[mt], sAl + ro);
            }
            uint32_t bh[8][2], bl[8][2];
            #pragma unroll
            for (int g = 0; g < 4; g++) {
                const uint32_t ro = (warp_n * 64 + g * 16 + lrow) * ROWB + coff;
                uint32_t r[4];
                ldm_x4(r, sBh + ro);
                bh[2 * g][0] = r[0]; bh[2 * g][1] = r[2];
                bh[2 * g + 1][0] = r[1]; bh[2 * g + 1][1] = r[3];
                ldm_x4(r, sBl + ro);
                bl[2 * g][0] = r[0]; bl[2 * g][1] = r[2];
                bl[2 * g + 1][0] = r[1]; bl[2 * g + 1][1] = r[3];
            }
            #pragma unroll
            for (int mt = 0; mt < 2; mt++)
                #pragma unroll
                for (int nt = 0; nt < 8; nt++)
                    mma16816(acc[mt][nt], ah[mt], bh[nt]);
            #pragma unroll
            for (int mt = 0; mt < 2; mt++)
                #pragma unroll
                for (int nt = 0; nt < 8; nt++)
                    mma16816(acc[mt][nt], ah[mt], bl[nt]);
            #pragma unroll
            for (int mt = 0; mt < 2; mt++)
                #pragma unroll
                for (int nt = 0; nt < 8; nt++)
                    mma16816(acc[mt][nt], al[mt], bh[nt]);
        }
        __syncthreads();
        if (c + 2 < nch) {
            uint32_t nb = sb + (c & 1) * BUFB;
            load_tile_p(nb + 0 * TILEB, Ahi, rowA, (c + 2) * 32, K, t);
            load_tile_p(nb + 1 * TILEB, Alo, rowA, (c + 2) * 32, K, t);
            load_tile_p(nb + 2 * TILEB, Bhi, rowB, (c + 2) * 32, K, t);
            load_tile_p(nb + 3 * TILEB, Blo, rowB, (c + 2) * 32, K, t);
            CP_COMMIT();
        }
    }

    // epilogue
    #pragma unroll
    for (int mt = 0; mt < 2; mt++) {
        const int r0 = blockIdx.y * 128 + warp_m * 32 + mt * 16 + (lane >> 2);
        #pragma unroll
        for (int nt = 0; nt < 8; nt++) {
            const int col = blockIdx.x * 128 + warp_n * 64 + nt * 8 + (lane & 3) * 2;
            if (MODE == 1) {
                const float2 b2 = *(const float2*)(bias + col);
                *(float2*)(Cf + (size_t)r0 * N + col) =
                    make_float2(acc[mt][nt][0] + b2.x, acc[mt][nt][1] + b2.y);
                *(float2*)(Cf + (size_t)(r0 + 8) * N + col) =
                    make_float2(acc[mt][nt][2] + b2.x, acc[mt][nt][3] + b2.y);
            } else {
                #pragma unroll
                for (int hrow = 0; hrow < 2; hrow++) {
                    const __half2 hv = __floats2half2_rn(acc[mt][nt][hrow * 2],
                                                         acc[mt][nt][hrow * 2 + 1]);
                    *(__half2*)(Ch + (size_t)(r0 + 8 * hrow) * N + col) = hv;
                }
            }
        }
    }
}

// ------------------------- fp16 flash attention -----------------------------
constexpr int AROWB = 144;
constexpr int QTILEB = 128 * AROWB;            // 18432
constexpr int KTILEB = 64 * AROWB;             // 9216
constexpr int KVBUF = 2 * KTILEB;              // K + V = 18432
constexpr int SMEM_ATT_BYTES = QTILEB + 2 * KVBUF;  // 55296

__device__ __forceinline__ void att_load(uint32_t dst, const __half* src,
                                         int rows256, int t) {
    #pragma unroll
    for (int i = 0; i < 4; i++) {
        if (i >= rows256) break;
        int s = i * 256 + t;
        int r = s >> 3, seg = (s & 7) * 16;
        cp_async16(dst + r * AROWB + seg, (const char*)src + (size_t)r * 6144 + seg);
    }
}

__global__ __launch_bounds__(256) void attn_mma(
    const __half* __restrict__ qkv,
    __nv_bfloat16* __restrict__ outhi, __nv_bfloat16* __restrict__ outlo)
{
    extern __shared__ char smem[];
    const uint32_t sb = smem_u32(smem);
    const int t = threadIdx.x, wid = t >> 5, lane = t & 31;
    const int bh_ = blockIdx.y, b = bh_ >> 4, h = bh_ & 15;
    const int q0 = blockIdx.x * 128;
    const size_t rb = (size_t)b * 2048;

    const uint32_t QT = sb;
    const uint32_t KV0 = sb + QTILEB;
    const __half* k_b = qkv + rb * 3072 + 1024 + h * 64;
    const __half* v_b = qkv + rb * 3072 + 2048 + h * 64;

    att_load(QT, qkv + (rb + q0) * 3072 + h * 64, 4, t);
    #pragma unroll
    for (int c = 0; c < 2; c++) {
        const uint32_t kb = KV0 + c * KVBUF;
        att_load(kb, k_b + (size_t)(c * 64) * 3072, 2, t);
        att_load(kb + KTILEB, v_b + (size_t)(c * 64) * 3072, 2, t);
        CP_COMMIT();
    }

    float oacc[8][4];
    #pragma unroll
    for (int nd = 0; nd < 8; nd++)
        #pragma unroll
        for (int j = 0; j < 4; j++) oacc[nd][j] = 0.f;
    float m0 = -1e30f, m1 = -1e30f, l0 = 0.f, l1 = 0.f;

    const int lrow = lane & 15;
    const uint32_t lcol = (lane >> 4) << 4;

    for (int c = 0; c < 32; c++) {
        if (c == 31) { CP_WAIT(0); } else { CP_WAIT(1); }
        __syncthreads();
        const uint32_t kb = KV0 + (c & 1) * KVBUF;
        const uint32_t sK = kb, sV = kb + KTILEB;

        // ---- S = Q K^T (fp16, single term) ----
        float sacc[8][4];
        #pragma unroll
        for (int nt = 0; nt < 8; nt++)
            #pragma unroll
            for (int j = 0; j < 4; j++) sacc[nt][j] = 0.f;

        #pragma unroll
        for (int kt = 0; kt < 4; kt++) {
            const uint32_t coff = kt * 32 + lcol;
            uint32_t q4[4];
            ldm_x4(q4, QT + (wid * 16 + lrow) * AROWB + coff);
            uint32_t bk[8][2];
            #pragma unroll
            for (int g = 0; g < 4; g++) {
                uint32_t r[4];
                ldm_x4(r, sK + (g * 16 + lrow) * AROWB + coff);
                bk[2 * g][0] = r[0]; bk[2 * g][1] = r[2];
                bk[2 * g + 1][0] = r[1]; bk[2 * g + 1][1] = r[3];
            }
            #pragma unroll
            for (int nt = 0; nt < 8; nt++)
                mma16816h(sacc[nt], q4, bk[nt]);
        }

        // ---- online softmax (log2 units) ----
        float tm0 = -1e30f, tm1 = -1e30f;
        #pragma unroll
        for (int nt = 0; nt < 8; nt++) {
            tm0 = fmaxf(tm0, fmaxf(sacc[nt][0], sacc[nt][1]));
            tm1 = fmaxf(tm1, fmaxf(sacc[nt][2], sacc[nt][3]));
        }
        tm0 = fmaxf(tm0, __shfl_xor_sync(0xffffffffu, tm0, 1));
        tm0 = fmaxf(tm0, __shfl_xor_sync(0xffffffffu, tm0, 2));
        tm1 = fmaxf(tm1, __shfl_xor_sync(0xffffffffu, tm1, 1));
        tm1 = fmaxf(tm1, __shfl_xor_sync(0xffffffffu, tm1, 2));
        const float nm0 = fmaxf(m0, tm0), nm1 = fmaxf(m1, tm1);
        const float cr0 = ex2(m0 - nm0), cr1 = ex2(m1 - nm1);
        m0 = nm0; m1 = nm1;
        l0 *= cr0; l1 *= cr1;
        #pragma unroll
        for (int nd = 0; nd < 8; nd++) {
            oacc[nd][0] *= cr0; oacc[nd][1] *= cr0;
            oacc[nd][2] *= cr1; oacc[nd][3] *= cr1;
        }
        float rs0 = 0.f, rs1 = 0.f;
        #pragma unroll
        for (int nt = 0; nt < 8; nt++) {
            float p0 = ex2(sacc[nt][0] - m0), p1 = ex2(sacc[nt][1] - m0);
            float p2 = ex2(sacc[nt][2] - m1), p3 = ex2(sacc[nt][3] - m1);
            sacc[nt][0] = p0; sacc[nt][1] = p1; sacc[nt][2] = p2; sacc[nt][3] = p3;
            rs0 += p0 + p1; rs1 += p2 + p3;
        }
        rs0 += __shfl_xor_sync(0xffffffffu, rs0, 1);
        rs0 += __shfl_xor_sync(0xffffffffu, rs0, 2);
        rs1 += __shfl_xor_sync(0xffffffffu, rs1, 1);
        rs1 += __shfl_xor_sync(0xffffffffu, rs1, 2);
        l0 += rs0; l1 += rs1;

        // ---- O += P V (fp16 P, single term) ----
        #pragma unroll
        for (int kt = 0; kt < 4; kt++) {
            uint32_t ap[4];
            #pragma unroll
            for (int half = 0; half < 2; half++) {
                const float* sp = sacc[2 * kt + half];
                ap[half * 2 + 0] = pack_f16x2(sp[0], sp[1]);
                ap[half * 2 + 1] = pack_f16x2(sp[2], sp[3]);
            }
            uint32_t bv[8][2];
            #pragma unroll
            for (int nd2 = 0; nd2 < 4; nd2++) {
                uint32_t r[4];
                ldm_x4_t(r, sV + (kt * 16 + lrow) * AROWB + nd2 * 32 + lcol);
                bv[2 * nd2][0] = r[0]; bv[2 * nd2][1] = r[1];
                bv[2 * nd2 + 1][0] = r[2]; bv[2 * nd2 + 1][1] = r[3];
            }
            #pragma unroll
            for (int nd = 0; nd < 8; nd++)
                mma16816h(oacc[nd], ap, bv[nd]);
        }

        __syncthreads();
        if (c + 2 < 32) {
            const uint32_t nb = KV0 + (c & 1) * KVBUF;
            const size_t j0 = (size_t)((c + 2) * 64) * 3072;
            att_load(nb, k_b + j0, 2, t);
            att_load(nb + KTILEB, v_b + j0, 2, t);
            CP_COMMIT();
        }
    }

    // ---- epilogue: normalize + split bf16 write ----
    const float inv0 = 1.f / l0, inv1 = 1.f / l1;
    const int r0 = q0 + wid * 16 + (lane >> 2);
    #pragma unroll
    for (int nd = 0; nd < 8; nd++) {
        const int col = h * 64 + nd * 8 + (lane & 3) * 2;
        #pragma unroll
        for (int hrow = 0; hrow < 2; hrow++) {
            const float inv = hrow ? inv1 : inv0;
            const float v0 = oacc[nd][hrow * 2] * inv;
            const float v1 = oacc[nd][hrow * 2 + 1] * inv;
            __nv_bfloat162 hh = __float22bfloat162_rn(make_float2(v0, v1));
            __nv_bfloat162 ll = __float22bfloat162_rn(
                make_float2(v0 - __low2float(hh), v1 - __high2float(hh)));
            const size_t off = (rb + r0 + 8 * hrow) * 1024 + col;
            *(__nv_bfloat162*)(outhi + off) = hh;
            *(__nv_bfloat162*)(outlo + off) = ll;
        }
    }
}

// ------------------------- launch ------------------------------------------
extern "C" void kernel_launch(void* const* d_in, const int* in_sizes, int n_in,
                              void* d_out, int out_size)
{
    const float* x     = (const float*)d_in[0];
    const float* w_qkv = (const float*)d_in[1];
    const float* w_out = (const float*)d_in[2];
    const float* b_out = (const float*)d_in[3];
    float* out = (float*)d_out;

    __nv_bfloat16 *xhi, *xlo, *wqh, *wql, *woh, *wol, *ahi, *alo;
    __half* qkv16;
    cudaGetSymbolAddress((void**)&xhi, g_xhi);
    cudaGetSymbolAddress((void**)&xlo, g_xlo);
    cudaGetSymbolAddress((void**)&wqh, g_wqkvt_hi);
    cudaGetSymbolAddress((void**)&wql, g_wqkvt_lo);
    cudaGetSymbolAddress((void**)&woh, g_woutt_hi);
    cudaGetSymbolAddress((void**)&wol, g_woutt_lo);
    cudaGetSymbolAddress((void**)&qkv16, g_qkv16);
    cudaGetSymbolAddress((void**)&ahi, g_atthi);
    cudaGetSymbolAddress((void**)&alo, g_attlo);

    cudaFuncSetAttribute(gemm_mma<0>, cudaFuncAttributeMaxDynamicSharedMemorySize,
                         SMEM_GEMM_BYTES);
    cudaFuncSetAttribute(gemm_mma<1>, cudaFuncAttributeMaxDynamicSharedMemorySize,
                         SMEM_GEMM_BYTES);
    cudaFuncSetAttribute(attn_mma, cudaFuncAttributeMaxDynamicSharedMemorySize,
                         SMEM_ATT_BYTES);

    split_fp32<<<(8192 * 1024 / 4 + 255) / 256, 256>>>(x, xhi, xlo, 8192 * 1024 / 4);
    transpose_split<<<dim3(3072 / 32, 1024 / 32), dim3(32, 8)>>>(
        w_qkv, wqh, wql, 1024, 3072, 1024, ATT_SCALE * LOG2E);
    transpose_split<<<dim3(1024 / 32, 1024 / 32), dim3(32, 8)>>>(
        w_out, woh, wol, 1024, 1024, 0, 1.f);

    // stage 1: qkv = x @ w_qkv (bf16 3-term, writes fp16)
    gemm_mma<0><<<dim3(3072 / 128, 8192 / 128), 256, SMEM_GEMM_BYTES>>>(
        xhi, xlo, wqh, wql, nullptr, qkv16, nullptr, 3072, 1024);

    // stage 2: flash attention (fp16 single-term), writes split bf16
    attn_mma<<<dim3(2048 / 128, 64), 256, SMEM_ATT_BYTES>>>(qkv16, ahi, alo);

    // stage 3: out = att @ w_out + b (bf16 3-term)
    gemm_mma<1><<<dim3(1024 / 128, 8192 / 128), 256, SMEM_GEMM_BYTES>>>(
        ahi, alo, woh, wol, b_out, nullptr, out, 1024, 1024);
}

// round 9
// speedup vs baseline: 7.1393x; 1.4307x over previous
#include <cuda_runtime.h>
#include <cuda_bf16.h>
#include <cuda_fp16.h>
#include <cstdint>

// ---------------------------------------------------------------------------
// Attention_71485435675049 — Round 9
// gemm0: fp16 single-term HMMA (3x fewer MMAs than R8's bf16 3-term).
// attention: fp16 single-term (validated R8).
// gemm1: bf16 hi/lo 3-term (error reserve).
// ---------------------------------------------------------------------------

#define ATT_SCALE 0.125f
#define LOG2E 1.4426950408889634f

// ------------------------- scratch (no allocs allowed) ----------------------
__device__ __half        g_x16[8192 * 1024];
__device__ __half        g_wqkvt16[3072 * 1024];    // [N,K] transposed fp16
__device__ __nv_bfloat16 g_woutt_hi[1024 * 1024];
__device__ __nv_bfloat16 g_woutt_lo[1024 * 1024];
__device__ __half        g_qkv16[8192 * 3072];
__device__ __nv_bfloat16 g_atthi[8192 * 1024];
__device__ __nv_bfloat16 g_attlo[8192 * 1024];

// ------------------------- PTX helpers -------------------------------------
__device__ __forceinline__ uint32_t smem_u32(const void* p) {
    uint32_t a;
    asm("{ .reg .u64 t; cvta.to.shared.u64 t, %1; cvt.u32.u64 %0, t; }"
        : "=r"(a) : "l"(p));
    return a;
}

__device__ __forceinline__ void cp_async16(uint32_t dst, const void* src) {
    asm volatile("cp.async.cg.shared.global [%0], [%1], 16;\n"
                 :: "r"(dst), "l"(src));
}
#define CP_COMMIT() asm volatile("cp.async.commit_group;\n" ::: "memory")
#define CP_WAIT(n)  asm volatile("cp.async.wait_group %0;\n" :: "n"(n) : "memory")

__device__ __forceinline__ void ldm_x4(uint32_t r[4], uint32_t addr) {
    asm volatile("ldmatrix.sync.aligned.m8n8.x4.shared.b16 {%0,%1,%2,%3}, [%4];"
                 : "=r"(r[0]), "=r"(r[1]), "=r"(r[2]), "=r"(r[3]) : "r"(addr));
}
__device__ __forceinline__ void ldm_x4_t(uint32_t r[4], uint32_t addr) {
    asm volatile("ldmatrix.sync.aligned.m8n8.x4.trans.shared.b16 {%0,%1,%2,%3}, [%4];"
                 : "=r"(r[0]), "=r"(r[1]), "=r"(r[2]), "=r"(r[3]) : "r"(addr));
}

__device__ __forceinline__ void mma16816(float c[4], const uint32_t a[4],
                                         const uint32_t b[2]) {
    asm volatile(
        "mma.sync.aligned.m16n8k16.row.col.f32.bf16.bf16.f32 "
        "{%0,%1,%2,%3}, {%4,%5,%6,%7}, {%8,%9}, {%0,%1,%2,%3};"
        : "+f"(c[0]), "+f"(c[1]), "+f"(c[2]), "+f"(c[3])
        : "r"(a[0]), "r"(a[1]), "r"(a[2]), "r"(a[3]), "r"(b[0]), "r"(b[1]));
}
__device__ __forceinline__ void mma16816h(float c[4], const uint32_t a[4],
                                          const uint32_t b[2]) {
    asm volatile(
        "mma.sync.aligned.m16n8k16.row.col.f32.f16.f16.f32 "
        "{%0,%1,%2,%3}, {%4,%5,%6,%7}, {%8,%9}, {%0,%1,%2,%3};"
        : "+f"(c[0]), "+f"(c[1]), "+f"(c[2]), "+f"(c[3])
        : "r"(a[0]), "r"(a[1]), "r"(a[2]), "r"(a[3]), "r"(b[0]), "r"(b[1]));
}

__device__ __forceinline__ float ex2(float x) {
    float r; asm("ex2.approx.f32 %0, %1;" : "=f"(r) : "f"(x)); return r;
}
__device__ __forceinline__ uint32_t pack_f16x2(float lo, float hi) {
    uint32_t d;
    asm("cvt.rn.f16x2.f32 %0, %1, %2;" : "=r"(d) : "f"(hi), "f"(lo));
    return d;
}

// ------------------------- conversion kernels ------------------------------
__global__ void convert_f16(const float* __restrict__ src,
                            __half* __restrict__ dst, int n4) {
    int i = blockIdx.x * blockDim.x + threadIdx.x;
    if (i >= n4) return;
    float4 v = ((const float4*)src)[i];
    __half2 a = __floats2half2_rn(v.x, v.y);
    __half2 b = __floats2half2_rn(v.z, v.w);
    ((__half2*)dst)[i * 2 + 0] = a;
    ((__half2*)dst)[i * 2 + 1] = b;
}

// src[K,N] fp32 -> out[N,K] fp16; cols < scale_cols scaled by `scale`
__global__ void transpose_f16(const float* __restrict__ src,
                              __half* __restrict__ dst,
                              int K, int N, int scale_cols, float scale) {
    __shared__ float tile[32][33];
    const int n0 = blockIdx.x * 32, k0 = blockIdx.y * 32;
    const int tx = threadIdx.x, ty = threadIdx.y;
    #pragma unroll
    for (int j = 0; j < 4; j++) {
        int r = ty + j * 8;
        float v = src[(size_t)(k0 + r) * N + n0 + tx];
        if (n0 + tx < scale_cols) v *= scale;
        tile[r][tx] = v;
    }
    __syncthreads();
    #pragma unroll
    for (int j = 0; j < 4; j++) {
        int b = ty + j * 8;
        dst[(size_t)(n0 + b) * K + k0 + tx] = __float2half_rn(tile[tx][b]);
    }
}

// src[K,N] fp32 -> out[N,K] bf16 hi/lo
__global__ void transpose_split(const float* __restrict__ src,
                                __nv_bfloat16* __restrict__ hi,
                                __nv_bfloat16* __restrict__ lo, int K, int N) {
    __shared__ float tile[32][33];
    const int n0 = blockIdx.x * 32, k0 = blockIdx.y * 32;
    const int tx = threadIdx.x, ty = threadIdx.y;
    #pragma unroll
    for (int j = 0; j < 4; j++) {
        int r = ty + j * 8;
        tile[r][tx] = src[(size_t)(k0 + r) * N + n0 + tx];
    }
    __syncthreads();
    #pragma unroll
    for (int j = 0; j < 4; j++) {
        int b = ty + j * 8;
        float v = tile[tx][b];
        __nv_bfloat16 h = __float2bfloat16(v);
        size_t o = (size_t)(n0 + b) * K + k0 + tx;
        hi[o] = h;
        lo[o] = __float2bfloat16(v - __bfloat162float(h));
    }
}

// ------------------------- shared GEMM pieces ------------------------------
constexpr int ROWB = 80;
constexpr int TILEB = 128 * ROWB;

__device__ __forceinline__ void load_tile_p(uint32_t dst, const void* src0,
                                            int row0, int k0, int K, int t) {
    const char* sp = (const char*)src0 + ((size_t)row0 * K + k0) * 2;
    const size_t rs = (size_t)K * 2;
    #pragma unroll
    for (int i = 0; i < 2; i++) {
        int s = i * 256 + t;
        int row = s >> 2, seg = (s & 3) * 16;
        cp_async16(dst + row * ROWB + seg, sp + (size_t)row * rs + seg);
    }
}

// ------------------------- fp16 single-term GEMM (stage 1) ------------------
constexpr int BUF16 = 2 * TILEB;              // A + B
constexpr int SMEM_G16_BYTES = 2 * BUF16;     // 40960

__global__ __launch_bounds__(256) void gemm_f16(
    const __half* __restrict__ A, const __half* __restrict__ B,
    __half* __restrict__ C, int N, int K)
{
    extern __shared__ char smem[];
    const uint32_t sb = smem_u32(smem);
    const int t = threadIdx.x, wid = t >> 5, lane = t & 31;
    const int warp_m = wid & 3, warp_n = wid >> 2;

    const int rowA = blockIdx.y * 128, rowB = blockIdx.x * 128;
    const int nch = K / 32;

    float acc[2][8][4];
    #pragma unroll
    for (int mt = 0; mt < 2; mt++)
        #pragma unroll
        for (int nt = 0; nt < 8; nt++)
            #pragma unroll
            for (int j = 0; j < 4; j++) acc[mt][nt][j] = 0.f;

    #pragma unroll
    for (int c = 0; c < 2; c++) {
        uint32_t bb = sb + (c & 1) * BUF16;
        load_tile_p(bb, A, rowA, c * 32, K, t);
        load_tile_p(bb + TILEB, B, rowB, c * 32, K, t);
        CP_COMMIT();
    }

    const int lrow = lane & 15;
    const uint32_t lcol = (lane >> 4) << 4;

    for (int c = 0; c < nch; c++) {
        if (c == nch - 1) { CP_WAIT(0); } else { CP_WAIT(1); }
        __syncthreads();
        const uint32_t bb = sb + (c & 1) * BUF16;
        const uint32_t sA = bb, sB = bb + TILEB;

        #pragma unroll
        for (int kk = 0; kk < 2; kk++) {
            const uint32_t coff = kk * 32 + lcol;
            uint32_t a4[2][4];
            #pragma unroll
            for (int mt = 0; mt < 2; mt++)
                ldm_x4(a4[mt], sA + (warp_m * 32 + mt * 16 + lrow) * ROWB + coff);
            uint32_t b2[8][2];
            #pragma unroll
            for (int g = 0; g < 4; g++) {
                uint32_t r[4];
                ldm_x4(r, sB + (warp_n * 64 + g * 16 + lrow) * ROWB + coff);
                b2[2 * g][0] = r[0]; b2[2 * g][1] = r[2];
                b2[2 * g + 1][0] = r[1]; b2[2 * g + 1][1] = r[3];
            }
            #pragma unroll
            for (int mt = 0; mt < 2; mt++)
                #pragma unroll
                for (int nt = 0; nt < 8; nt++)
                    mma16816h(acc[mt][nt], a4[mt], b2[nt]);
        }
        __syncthreads();
        if (c + 2 < nch) {
            uint32_t nb = sb + (c & 1) * BUF16;
            load_tile_p(nb, A, rowA, (c + 2) * 32, K, t);
            load_tile_p(nb + TILEB, B, rowB, (c + 2) * 32, K, t);
            CP_COMMIT();
        }
    }

    #pragma unroll
    for (int mt = 0; mt < 2; mt++) {
        const int r0 = blockIdx.y * 128 + warp_m * 32 + mt * 16 + (lane >> 2);
        #pragma unroll
        for (int nt = 0; nt < 8; nt++) {
            const int col = blockIdx.x * 128 + warp_n * 64 + nt * 8 + (lane & 3) * 2;
            #pragma unroll
            for (int hrow = 0; hrow < 2; hrow++) {
                const __half2 hv = __floats2half2_rn(acc[mt][nt][hrow * 2],
                                                     acc[mt][nt][hrow * 2 + 1]);
                *(__half2*)(C + (size_t)(r0 + 8 * hrow) * N + col) = hv;
            }
        }
    }
}

// ------------------------- bf16 3-term GEMM (stage 3) -----------------------
constexpr int BUFB = 4 * TILEB;
constexpr int SMEM_GEMM_BYTES = 2 * BUFB;     // 81920

__global__ __launch_bounds__(256) void gemm_mma1(
    const __nv_bfloat16* __restrict__ Ahi, const __nv_bfloat16* __restrict__ Alo,
    const __nv_bfloat16* __restrict__ Bhi, const __nv_bfloat16* __restrict__ Blo,
    const float* __restrict__ bias, float* __restrict__ Cf, int N, int K)
{
    extern __shared__ char smem[];
    const uint32_t sb = smem_u32(smem);
    const int t = threadIdx.x, wid = t >> 5, lane = t & 31;
    const int warp_m = wid & 3, warp_n = wid >> 2;

    const int rowA = blockIdx.y * 128, rowB = blockIdx.x * 128;
    const int nch = K / 32;

    float acc[2][8][4];
    #pragma unroll
    for (int mt = 0; mt < 2; mt++)
        #pragma unroll
        for (int nt = 0; nt < 8; nt++)
            #pragma unroll
            for (int j = 0; j < 4; j++) acc[mt][nt][j] = 0.f;

    #pragma unroll
    for (int c = 0; c < 2; c++) {
        uint32_t bb = sb + (c & 1) * BUFB;
        load_tile_p(bb + 0 * TILEB, Ahi, rowA, c * 32, K, t);
        load_tile_p(bb + 1 * TILEB, Alo, rowA, c * 32, K, t);
        load_tile_p(bb + 2 * TILEB, Bhi, rowB, c * 32, K, t);
        load_tile_p(bb + 3 * TILEB, Blo, rowB, c * 32, K, t);
        CP_COMMIT();
    }

    const int lrow = lane & 15;
    const uint32_t lcol = (lane >> 4) << 4;

    for (int c = 0; c < nch; c++) {
        if (c == nch - 1) { CP_WAIT(0); } else { CP_WAIT(1); }
        __syncthreads();
        const uint32_t bb = sb + (c & 1) * BUFB;
        const uint32_t sAh = bb, sAl = bb + TILEB;
        const uint32_t sBh = bb + 2 * TILEB, sBl = bb + 3 * TILEB;

        #pragma unroll
        for (int kk = 0; kk < 2; kk++) {
            const uint32_t coff = kk * 32 + lcol;
            uint32_t ah[2][4], al[2][4];
            #pragma unroll
            for (int mt = 0; mt < 2; mt++) {
                const uint32_t ro = (warp_m * 32 + mt * 16 + lrow) * ROWB + coff;
                ldm_x4(ah[mt], sAh + ro);
                ldm_x4(al[mt], sAl + ro);
            }
            uint32_t bh[8][2], bl[8][2];
            #pragma unroll
            for (int g = 0; g < 4; g++) {
                const uint32_t ro = (warp_n * 64 + g * 16 + lrow) * ROWB + coff;
                uint32_t r[4];
                ldm_x4(r, sBh + ro);
                bh[2 * g][0] = r[0]; bh[2 * g][1] = r[2];
                bh[2 * g + 1][0] = r[1]; bh[2 * g + 1][1] = r[3];
                ldm_x4(r, sBl + ro);
                bl[2 * g][0] = r[0]; bl[2 * g][1] = r[2];
                bl[2 * g + 1][0] = r[1]; bl[2 * g + 1][1] = r[3];
            }
            #pragma unroll
            for (int mt = 0; mt < 2; mt++)
                #pragma unroll
                for (int nt = 0; nt < 8; nt++)
                    mma16816(acc[mt][nt], ah[mt], bh[nt]);
            #pragma unroll
            for (int mt = 0; mt < 2; mt++)
                #pragma unroll
                for (int nt = 0; nt < 8; nt++)
                    mma16816(acc[mt][nt], ah[mt], bl[nt]);
            #pragma unroll
            for (int mt = 0; mt < 2; mt++)
                #pragma unroll
                for (int nt = 0; nt < 8; nt++)
                    mma16816(acc[mt][nt], al[mt], bh[nt]);
        }
        __syncthreads();
        if (c + 2 < nch) {
            uint32_t nb = sb + (c & 1) * BUFB;
            load_tile_p(nb + 0 * TILEB, Ahi, rowA, (c + 2) * 32, K, t);
            load_tile_p(nb + 1 * TILEB, Alo, rowA, (c + 2) * 32, K, t);
            load_tile_p(nb + 2 * TILEB, Bhi, rowB, (c + 2) * 32, K, t);
            load_tile_p(nb + 3 * TILEB, Blo, rowB, (c + 2) * 32, K, t);
            CP_COMMIT();
        }
    }

    #pragma unroll
    for (int mt = 0; mt < 2; mt++) {
        const int r0 = blockIdx.y * 128 + warp_m * 32 + mt * 16 + (lane >> 2);
        #pragma unroll
        for (int nt = 0; nt < 8; nt++) {
            const int col = blockIdx.x * 128 + warp_n * 64 + nt * 8 + (lane & 3) * 2;
            const float2 b2 = *(const float2*)(bias + col);
            *(float2*)(Cf + (size_t)r0 * N + col) =
                make_float2(acc[mt][nt][0] + b2.x, acc[mt][nt][1] + b2.y);
            *(float2*)(Cf + (size_t)(r0 + 8) * N + col) =
                make_float2(acc[mt][nt][2] + b2.x, acc[mt][nt][3] + b2.y);
        }
    }
}

// ------------------------- fp16 flash attention -----------------------------
constexpr int AROWB = 144;
constexpr int QTILEB = 128 * AROWB;
constexpr int KTILEB = 64 * AROWB;
constexpr int KVBUF = 2 * KTILEB;
constexpr int SMEM_ATT_BYTES = QTILEB + 2 * KVBUF;  // 55296

__device__ __forceinline__ void att_load(uint32_t dst, const __half* src,
                                         int rows256, int t) {
    #pragma unroll
    for (int i = 0; i < 4; i++) {
        if (i >= rows256) break;
        int s = i * 256 + t;
        int r = s >> 3, seg = (s & 7) * 16;
        cp_async16(dst + r * AROWB + seg, (const char*)src + (size_t)r * 6144 + seg);
    }
}

__global__ __launch_bounds__(256) void attn_mma(
    const __half* __restrict__ qkv,
    __nv_bfloat16* __restrict__ outhi, __nv_bfloat16* __restrict__ outlo)
{
    extern __shared__ char smem[];
    const uint32_t sb = smem_u32(smem);
    const int t = threadIdx.x, wid = t >> 5, lane = t & 31;
    const int bh_ = blockIdx.y, b = bh_ >> 4, h = bh_ & 15;
    const int q0 = blockIdx.x * 128;
    const size_t rb = (size_t)b * 2048;

    const uint32_t QT = sb;
    const uint32_t KV0 = sb + QTILEB;
    const __half* k_b = qkv + rb * 3072 + 1024 + h * 64;
    const __half* v_b = qkv + rb * 3072 + 2048 + h * 64;

    att_load(QT, qkv + (rb + q0) * 3072 + h * 64, 4, t);
    #pragma unroll
    for (int c = 0; c < 2; c++) {
        const uint32_t kb = KV0 + c * KVBUF;
        att_load(kb, k_b + (size_t)(c * 64) * 3072, 2, t);
        att_load(kb + KTILEB, v_b + (size_t)(c * 64) * 3072, 2, t);
        CP_COMMIT();
    }

    float oacc[8][4];
    #pragma unroll
    for (int nd = 0; nd < 8; nd++)
        #pragma unroll
        for (int j = 0; j < 4; j++) oacc[nd][j] = 0.f;
    float m0 = -1e30f, m1 = -1e30f, l0 = 0.f, l1 = 0.f;

    const int lrow = lane & 15;
    const uint32_t lcol = (lane >> 4) << 4;

    for (int c = 0; c < 32; c++) {
        if (c == 31) { CP_WAIT(0); } else { CP_WAIT(1); }
        __syncthreads();
        const uint32_t kb = KV0 + (c & 1) * KVBUF;
        const uint32_t sK = kb, sV = kb + KTILEB;

        float sacc[8][4];
        #pragma unroll
        for (int nt = 0; nt < 8; nt++)
            #pragma unroll
            for (int j = 0; j < 4; j++) sacc[nt][j] = 0.f;

        #pragma unroll
        for (int kt = 0; kt < 4; kt++) {
            const uint32_t coff = kt * 32 + lcol;
            uint32_t q4[4];
            ldm_x4(q4, QT + (wid * 16 + lrow) * AROWB + coff);
            uint32_t bk[8][2];
            #pragma unroll
            for (int g = 0; g < 4; g++) {
                uint32_t r[4];
                ldm_x4(r, sK + (g * 16 + lrow) * AROWB + coff);
                bk[2 * g][0] = r[0]; bk[2 * g][1] = r[2];
                bk[2 * g + 1][0] = r[1]; bk[2 * g + 1][1] = r[3];
            }
            #pragma unroll
            for (int nt = 0; nt < 8; nt++)
                mma16816h(sacc[nt], q4, bk[nt]);
        }

        float tm0 = -1e30f, tm1 = -1e30f;
        #pragma unroll
        for (int nt = 0; nt < 8; nt++) {
            tm0 = fmaxf(tm0, fmaxf(sacc[nt][0], sacc[nt][1]));
            tm1 = fmaxf(tm1, fmaxf(sacc[nt][2], sacc[nt][3]));
        }
        tm0 = fmaxf(tm0, __shfl_xor_sync(0xffffffffu, tm0, 1));
        tm0 = fmaxf(tm0, __shfl_xor_sync(0xffffffffu, tm0, 2));
        tm1 = fmaxf(tm1, __shfl_xor_sync(0xffffffffu, tm1, 1));
        tm1 = fmaxf(tm1, __shfl_xor_sync(0xffffffffu, tm1, 2));
        const float nm0 = fmaxf(m0, tm0), nm1 = fmaxf(m1, tm1);
        const float cr0 = ex2(m0 - nm0), cr1 = ex2(m1 - nm1);
        m0 = nm0; m1 = nm1;
        l0 *= cr0; l1 *= cr1;
        #pragma unroll
        for (int nd = 0; nd < 8; nd++) {
            oacc[nd][0] *= cr0; oacc[nd][1] *= cr0;
            oacc[nd][2] *= cr1; oacc[nd][3] *= cr1;
        }
        float rs0 = 0.f, rs1 = 0.f;
        #pragma unroll
        for (int nt = 0; nt < 8; nt++) {
            float p0 = ex2(sacc[nt][0] - m0), p1 = ex2(sacc[nt][1] - m0);
            float p2 = ex2(sacc[nt][2] - m1), p3 = ex2(sacc[nt][3] - m1);
            sacc[nt][0] = p0; sacc[nt][1] = p1; sacc[nt][2] = p2; sacc[nt][3] = p3;
            rs0 += p0 + p1; rs1 += p2 + p3;
        }
        rs0 += __shfl_xor_sync(0xffffffffu, rs0, 1);
        rs0 += __shfl_xor_sync(0xffffffffu, rs0, 2);
        rs1 += __shfl_xor_sync(0xffffffffu, rs1, 1);
        rs1 += __shfl_xor_sync(0xffffffffu, rs1, 2);
        l0 += rs0; l1 += rs1;

        #pragma unroll
        for (int kt = 0; kt < 4; kt++) {
            uint32_t ap[4];
            #pragma unroll
            for (int half = 0; half < 2; half++) {
                const float* sp = sacc[2 * kt + half];
                ap[half * 2 + 0] = pack_f16x2(sp[0], sp[1]);
                ap[half * 2 + 1] = pack_f16x2(sp[2], sp[3]);
            }
            uint32_t bv[8][2];
            #pragma unroll
            for (int nd2 = 0; nd2 < 4; nd2++) {
                uint32_t r[4];
                ldm_x4_t(r, sV + (kt * 16 + lrow) * AROWB + nd2 * 32 + lcol);
                bv[2 * nd2][0] = r[0]; bv[2 * nd2][1] = r[1];
                bv[2 * nd2 + 1][0] = r[2]; bv[2 * nd2 + 1][1] = r[3];
            }
            #pragma unroll
            for (int nd = 0; nd < 8; nd++)
                mma16816h(oacc[nd], ap, bv[nd]);
        }

        __syncthreads();
        if (c + 2 < 32) {
            const uint32_t nb = KV0 + (c & 1) * KVBUF;
            const size_t j0 = (size_t)((c + 2) * 64) * 3072;
            att_load(nb, k_b + j0, 2, t);
            att_load(nb + KTILEB, v_b + j0, 2, t);
            CP_COMMIT();
        }
    }

    const float inv0 = 1.f / l0, inv1 = 1.f / l1;
    const int r0 = q0 + wid * 16 + (lane >> 2);
    #pragma unroll
    for (int nd = 0; nd < 8; nd++) {
        const int col = h * 64 + nd * 8 + (lane & 3) * 2;
        #pragma unroll
        for (int hrow = 0; hrow < 2; hrow++) {
            const float inv = hrow ? inv1 : inv0;
            const float v0 = oacc[nd][hrow * 2] * inv;
            const float v1 = oacc[nd][hrow * 2 + 1] * inv;
            __nv_bfloat162 hh = __float22bfloat162_rn(make_float2(v0, v1));
            __nv_bfloat162 ll = __float22bfloat162_rn(
                make_float2(v0 - __low2float(hh), v1 - __high2float(hh)));
            const size_t off = (rb + r0 + 8 * hrow) * 1024 + col;
            *(__nv_bfloat162*)(outhi + off) = hh;
            *(__nv_bfloat162*)(outlo + off) = ll;
        }
    }
}

// ------------------------- launch ------------------------------------------
extern "C" void kernel_launch(void* const* d_in, const int* in_sizes, int n_in,
                              void* d_out, int out_size)
{
    const float* x     = (const float*)d_in[0];
    const float* w_qkv = (const float*)d_in[1];
    const float* w_out = (const float*)d_in[2];
    const float* b_out = (const float*)d_in[3];
    float* out = (float*)d_out;

    __half *x16, *wq16, *qkv16;
    __nv_bfloat16 *woh, *wol, *ahi, *alo;
    cudaGetSymbolAddress((void**)&x16, g_x16);
    cudaGetSymbolAddress((void**)&wq16, g_wqkvt16);
    cudaGetSymbolAddress((void**)&woh, g_woutt_hi);
    cudaGetSymbolAddress((void**)&wol, g_woutt_lo);
    cudaGetSymbolAddress((void**)&qkv16, g_qkv16);
    cudaGetSymbolAddress((void**)&ahi, g_atthi);
    cudaGetSymbolAddress((void**)&alo, g_attlo);

    cudaFuncSetAttribute(gemm_f16, cudaFuncAttributeMaxDynamicSharedMemorySize,
                         SMEM_G16_BYTES);
    cudaFuncSetAttribute(gemm_mma1, cudaFuncAttributeMaxDynamicSharedMemorySize,
                         SMEM_GEMM_BYTES);
    cudaFuncSetAttribute(attn_mma, cudaFuncAttributeMaxDynamicSharedMemorySize,
                         SMEM_ATT_BYTES);

    // prep
    convert_f16<<<(8192 * 1024 / 4 + 255) / 256, 256>>>(x, x16, 8192 * 1024 / 4);
    transpose_f16<<<dim3(3072 / 32, 1024 / 32), dim3(32, 8)>>>(
        w_qkv, wq16, 1024, 3072, 1024, ATT_SCALE * LOG2E);
    transpose_split<<<dim3(1024 / 32, 1024 / 32), dim3(32, 8)>>>(
        w_out, woh, wol, 1024, 1024);

    // stage 1: qkv = x @ w_qkv (fp16 single-term)
    gemm_f16<<<dim3(3072 / 128, 8192 / 128), 256, SMEM_G16_BYTES>>>(
        x16, wq16, qkv16, 3072, 1024);

    // stage 2: flash attention (fp16), writes split bf16
    attn_mma<<<dim3(2048 / 128, 64), 256, SMEM_ATT_BYTES>>>(qkv16, ahi, alo);

    // stage 3: out = att @ w_out + b (bf16 3-term, error reserve)
    gemm_mma1<<<dim3(1024 / 128, 8192 / 128), 256, SMEM_GEMM_BYTES>>>(
        ahi, alo, woh, wol, b_out, out, 1024, 1024);
}

// round 10
// speedup vs baseline: 8.7373x; 1.2238x over previous
#include <cuda_runtime.h>
#include <cuda_bf16.h>
#include <cuda_fp16.h>
#include <cstdint>

// ---------------------------------------------------------------------------
// Attention_71485435675049 — Round 10
// All stages fp16 single-term HMMA. Attention writes fp16 att directly;
// one GEMM kernel serves stage 1 (fp16 out) and stage 3 (fp32 + bias).
// ---------------------------------------------------------------------------

#define ATT_SCALE 0.125f
#define LOG2E 1.4426950408889634f

// ------------------------- scratch (no allocs allowed) ----------------------
__device__ __half g_x16[8192 * 1024];
__device__ __half g_wqkvt16[3072 * 1024];    // [N,K] transposed fp16
__device__ __half g_woutt16[1024 * 1024];    // [N,K] transposed fp16
__device__ __half g_qkv16[8192 * 3072];
__device__ __half g_att16[8192 * 1024];

// ------------------------- PTX helpers -------------------------------------
__device__ __forceinline__ uint32_t smem_u32(const void* p) {
    uint32_t a;
    asm("{ .reg .u64 t; cvta.to.shared.u64 t, %1; cvt.u32.u64 %0, t; }"
        : "=r"(a) : "l"(p));
    return a;
}

__device__ __forceinline__ void cp_async16(uint32_t dst, const void* src) {
    asm volatile("cp.async.cg.shared.global [%0], [%1], 16;\n"
                 :: "r"(dst), "l"(src));
}
#define CP_COMMIT() asm volatile("cp.async.commit_group;\n" ::: "memory")
#define CP_WAIT(n)  asm volatile("cp.async.wait_group %0;\n" :: "n"(n) : "memory")

__device__ __forceinline__ void ldm_x4(uint32_t r[4], uint32_t addr) {
    asm volatile("ldmatrix.sync.aligned.m8n8.x4.shared.b16 {%0,%1,%2,%3}, [%4];"
                 : "=r"(r[0]), "=r"(r[1]), "=r"(r[2]), "=r"(r[3]) : "r"(addr));
}
__device__ __forceinline__ void ldm_x4_t(uint32_t r[4], uint32_t addr) {
    asm volatile("ldmatrix.sync.aligned.m8n8.x4.trans.shared.b16 {%0,%1,%2,%3}, [%4];"
                 : "=r"(r[0]), "=r"(r[1]), "=r"(r[2]), "=r"(r[3]) : "r"(addr));
}

__device__ __forceinline__ void mma16816h(float c[4], const uint32_t a[4],
                                          const uint32_t b[2]) {
    asm volatile(
        "mma.sync.aligned.m16n8k16.row.col.f32.f16.f16.f32 "
        "{%0,%1,%2,%3}, {%4,%5,%6,%7}, {%8,%9}, {%0,%1,%2,%3};"
        : "+f"(c[0]), "+f"(c[1]), "+f"(c[2]), "+f"(c[3])
        : "r"(a[0]), "r"(a[1]), "r"(a[2]), "r"(a[3]), "r"(b[0]), "r"(b[1]));
}

__device__ __forceinline__ float ex2(float x) {
    float r; asm("ex2.approx.f32 %0, %1;" : "=f"(r) : "f"(x)); return r;
}
__device__ __forceinline__ uint32_t pack_f16x2(float lo, float hi) {
    uint32_t d;
    asm("cvt.rn.f16x2.f32 %0, %1, %2;" : "=r"(d) : "f"(hi), "f"(lo));
    return d;
}

// ------------------------- conversion kernels ------------------------------
__global__ void convert_f16(const float* __restrict__ src,
                            __half* __restrict__ dst, int n4) {
    int i = blockIdx.x * blockDim.x + threadIdx.x;
    if (i >= n4) return;
    float4 v = ((const float4*)src)[i];
    ((__half2*)dst)[i * 2 + 0] = __floats2half2_rn(v.x, v.y);
    ((__half2*)dst)[i * 2 + 1] = __floats2half2_rn(v.z, v.w);
}

// src[K,N] fp32 -> out[N,K] fp16; cols < scale_cols scaled by `scale`
__global__ void transpose_f16(const float* __restrict__ src,
                              __half* __restrict__ dst,
                              int K, int N, int scale_cols, float scale) {
    __shared__ float tile[32][33];
    const int n0 = blockIdx.x * 32, k0 = blockIdx.y * 32;
    const int tx = threadIdx.x, ty = threadIdx.y;
    #pragma unroll
    for (int j = 0; j < 4; j++) {
        int r = ty + j * 8;
        float v = src[(size_t)(k0 + r) * N + n0 + tx];
        if (n0 + tx < scale_cols) v *= scale;
        tile[r][tx] = v;
    }
    __syncthreads();
    #pragma unroll
    for (int j = 0; j < 4; j++) {
        int b = ty + j * 8;
        dst[(size_t)(n0 + b) * K + k0 + tx] = __float2half_rn(tile[tx][b]);
    }
}

// ------------------------- fp16 single-term GEMM ----------------------------
constexpr int ROWB = 80;
constexpr int TILEB = 128 * ROWB;
constexpr int BUF16 = 2 * TILEB;              // A + B
constexpr int SMEM_G16_BYTES = 2 * BUF16;     // 40960

__device__ __forceinline__ void load_tile_p(uint32_t dst, const void* src0,
                                            int row0, int k0, int K, int t) {
    const char* sp = (const char*)src0 + ((size_t)row0 * K + k0) * 2;
    const size_t rs = (size_t)K * 2;
    #pragma unroll
    for (int i = 0; i < 2; i++) {
        int s = i * 256 + t;
        int row = s >> 2, seg = (s & 3) * 16;
        cp_async16(dst + row * ROWB + seg, sp + (size_t)row * rs + seg);
    }
}

// MODE 0: write fp16 C. MODE 1: write fp32 C + bias.
template <int MODE>
__global__ __launch_bounds__(256) void gemm_f16(
    const __half* __restrict__ A, const __half* __restrict__ B,
    const float* __restrict__ bias,
    __half* __restrict__ Ch, float* __restrict__ Cf, int N, int K)
{
    extern __shared__ char smem[];
    const uint32_t sb = smem_u32(smem);
    const int t = threadIdx.x, wid = t >> 5, lane = t & 31;
    const int warp_m = wid & 3, warp_n = wid >> 2;

    const int rowA = blockIdx.y * 128, rowB = blockIdx.x * 128;
    const int nch = K / 32;

    float acc[2][8][4];
    #pragma unroll
    for (int mt = 0; mt < 2; mt++)
        #pragma unroll
        for (int nt = 0; nt < 8; nt++)
            #pragma unroll
            for (int j = 0; j < 4; j++) acc[mt][nt][j] = 0.f;

    #pragma unroll
    for (int c = 0; c < 2; c++) {
        uint32_t bb = sb + (c & 1) * BUF16;
        load_tile_p(bb, A, rowA, c * 32, K, t);
        load_tile_p(bb + TILEB, B, rowB, c * 32, K, t);
        CP_COMMIT();
    }

    const int lrow = lane & 15;
    const uint32_t lcol = (lane >> 4) << 4;

    for (int c = 0; c < nch; c++) {
        if (c == nch - 1) { CP_WAIT(0); } else { CP_WAIT(1); }
        __syncthreads();
        const uint32_t bb = sb + (c & 1) * BUF16;
        const uint32_t sA = bb, sB = bb + TILEB;

        #pragma unroll
        for (int kk = 0; kk < 2; kk++) {
            const uint32_t coff = kk * 32 + lcol;
            uint32_t a4[2][4];
            #pragma unroll
            for (int mt = 0; mt < 2; mt++)
                ldm_x4(a4[mt], sA + (warp_m * 32 + mt * 16 + lrow) * ROWB + coff);
            uint32_t b2[8][2];
            #pragma unroll
            for (int g = 0; g < 4; g++) {
                uint32_t r[4];
                ldm_x4(r, sB + (warp_n * 64 + g * 16 + lrow) * ROWB + coff);
                b2[2 * g][0] = r[0]; b2[2 * g][1] = r[2];
                b2[2 * g + 1][0] = r[1]; b2[2 * g + 1][1] = r[3];
            }
            #pragma unroll
            for (int mt = 0; mt < 2; mt++)
                #pragma unroll
                for (int nt = 0; nt < 8; nt++)
                    mma16816h(acc[mt][nt], a4[mt], b2[nt]);
        }
        __syncthreads();
        if (c + 2 < nch) {
            uint32_t nb = sb + (c & 1) * BUF16;
            load_tile_p(nb, A, rowA, (c + 2) * 32, K, t);
            load_tile_p(nb + TILEB, B, rowB, (c + 2) * 32, K, t);
            CP_COMMIT();
        }
    }

    #pragma unroll
    for (int mt = 0; mt < 2; mt++) {
        const int r0 = blockIdx.y * 128 + warp_m * 32 + mt * 16 + (lane >> 2);
        #pragma unroll
        for (int nt = 0; nt < 8; nt++) {
            const int col = blockIdx.x * 128 + warp_n * 64 + nt * 8 + (lane & 3) * 2;
            if (MODE == 1) {
                const float2 b2 = *(const float2*)(bias + col);
                *(float2*)(Cf + (size_t)r0 * N + col) =
                    make_float2(acc[mt][nt][0] + b2.x, acc[mt][nt][1] + b2.y);
                *(float2*)(Cf + (size_t)(r0 + 8) * N + col) =
                    make_float2(acc[mt][nt][2] + b2.x, acc[mt][nt][3] + b2.y);
            } else {
                #pragma unroll
                for (int hrow = 0; hrow < 2; hrow++) {
                    const __half2 hv = __floats2half2_rn(acc[mt][nt][hrow * 2],
                                                         acc[mt][nt][hrow * 2 + 1]);
                    *(__half2*)(Ch + (size_t)(r0 + 8 * hrow) * N + col) = hv;
                }
            }
        }
    }
}

// ------------------------- fp16 flash attention -----------------------------
constexpr int AROWB = 144;
constexpr int QTILEB = 128 * AROWB;
constexpr int KTILEB = 64 * AROWB;
constexpr int KVBUF = 2 * KTILEB;
constexpr int SMEM_ATT_BYTES = QTILEB + 2 * KVBUF;  // 55296

__device__ __forceinline__ void att_load(uint32_t dst, const __half* src,
                                         int rows256, int t) {
    #pragma unroll
    for (int i = 0; i < 4; i++) {
        if (i >= rows256) break;
        int s = i * 256 + t;
        int r = s >> 3, seg = (s & 7) * 16;
        cp_async16(dst + r * AROWB + seg, (const char*)src + (size_t)r * 6144 + seg);
    }
}

__global__ __launch_bounds__(256) void attn_mma(
    const __half* __restrict__ qkv, __half* __restrict__ att)
{
    extern __shared__ char smem[];
    const uint32_t sb = smem_u32(smem);
    const int t = threadIdx.x, wid = t >> 5, lane = t & 31;
    const int bh_ = blockIdx.y, b = bh_ >> 4, h = bh_ & 15;
    const int q0 = blockIdx.x * 128;
    const size_t rb = (size_t)b * 2048;

    const uint32_t QT = sb;
    const uint32_t KV0 = sb + QTILEB;
    const __half* k_b = qkv + rb * 3072 + 1024 + h * 64;
    const __half* v_b = qkv + rb * 3072 + 2048 + h * 64;

    att_load(QT, qkv + (rb + q0) * 3072 + h * 64, 4, t);
    #pragma unroll
    for (int c = 0; c < 2; c++) {
        const uint32_t kb = KV0 + c * KVBUF;
        att_load(kb, k_b + (size_t)(c * 64) * 3072, 2, t);
        att_load(kb + KTILEB, v_b + (size_t)(c * 64) * 3072, 2, t);
        CP_COMMIT();
    }

    float oacc[8][4];
    #pragma unroll
    for (int nd = 0; nd < 8; nd++)
        #pragma unroll
        for (int j = 0; j < 4; j++) oacc[nd][j] = 0.f;
    float m0 = -1e30f, m1 = -1e30f, l0 = 0.f, l1 = 0.f;

    const int lrow = lane & 15;
    const uint32_t lcol = (lane >> 4) << 4;

    for (int c = 0; c < 32; c++) {
        if (c == 31) { CP_WAIT(0); } else { CP_WAIT(1); }
        __syncthreads();
        const uint32_t kb = KV0 + (c & 1) * KVBUF;
        const uint32_t sK = kb, sV = kb + KTILEB;

        float sacc[8][4];
        #pragma unroll
        for (int nt = 0; nt < 8; nt++)
            #pragma unroll
            for (int j = 0; j < 4; j++) sacc[nt][j] = 0.f;

        #pragma unroll
        for (int kt = 0; kt < 4; kt++) {
            const uint32_t coff = kt * 32 + lcol;
            uint32_t q4[4];
            ldm_x4(q4, QT + (wid * 16 + lrow) * AROWB + coff);
            uint32_t bk[8][2];
            #pragma unroll
            for (int g = 0; g < 4; g++) {
                uint32_t r[4];
                ldm_x4(r, sK + (g * 16 + lrow) * AROWB + coff);
                bk[2 * g][0] = r[0]; bk[2 * g][1] = r[2];
                bk[2 * g + 1][0] = r[1]; bk[2 * g + 1][1] = r[3];
            }
            #pragma unroll
            for (int nt = 0; nt < 8; nt++)
                mma16816h(sacc[nt], q4, bk[nt]);
        }

        float tm0 = -1e30f, tm1 = -1e30f;
        #pragma unroll
        for (int nt = 0; nt < 8; nt++) {
            tm0 = fmaxf(tm0, fmaxf(sacc[nt][0], sacc[nt][1]));
            tm1 = fmaxf(tm1, fmaxf(sacc[nt][2], sacc[nt][3]));
        }
        tm0 = fmaxf(tm0, __shfl_xor_sync(0xffffffffu, tm0, 1));
        tm0 = fmaxf(tm0, __shfl_xor_sync(0xffffffffu, tm0, 2));
        tm1 = fmaxf(tm1, __shfl_xor_sync(0xffffffffu, tm1, 1));
        tm1 = fmaxf(tm1, __shfl_xor_sync(0xffffffffu, tm1, 2));
        const float nm0 = fmaxf(m0, tm0), nm1 = fmaxf(m1, tm1);
        const float cr0 = ex2(m0 - nm0), cr1 = ex2(m1 - nm1);
        m0 = nm0; m1 = nm1;
        l0 *= cr0; l1 *= cr1;
        #pragma unroll
        for (int nd = 0; nd < 8; nd++) {
            oacc[nd][0] *= cr0; oacc[nd][1] *= cr0;
            oacc[nd][2] *= cr1; oacc[nd][3] *= cr1;
        }
        float rs0 = 0.f, rs1 = 0.f;
        #pragma unroll
        for (int nt = 0; nt < 8; nt++) {
            float p0 = ex2(sacc[nt][0] - m0), p1 = ex2(sacc[nt][1] - m0);
            float p2 = ex2(sacc[nt][2] - m1), p3 = ex2(sacc[nt][3] - m1);
            sacc[nt][0] = p0; sacc[nt][1] = p1; sacc[nt][2] = p2; sacc[nt][3] = p3;
            rs0 += p0 + p1; rs1 += p2 + p3;
        }
        rs0 += __shfl_xor_sync(0xffffffffu, rs0, 1);
        rs0 += __shfl_xor_sync(0xffffffffu, rs0, 2);
        rs1 += __shfl_xor_sync(0xffffffffu, rs1, 1);
        rs1 += __shfl_xor_sync(0xffffffffu, rs1, 2);
        l0 += rs0; l1 += rs1;

        #pragma unroll
        for (int kt = 0; kt < 4; kt++) {
            uint32_t ap[4];
            #pragma unroll
            for (int half = 0; half < 2; half++) {
                const float* sp = sacc[2 * kt + half];
                ap[half * 2 + 0] = pack_f16x2(sp[0], sp[1]);
                ap[half * 2 + 1] = pack_f16x2(sp[2], sp[3]);
            }
            uint32_t bv[8][2];
            #pragma unroll
            for (int nd2 = 0; nd2 < 4; nd2++) {
                uint32_t r[4];
                ldm_x4_t(r, sV + (kt * 16 + lrow) * AROWB + nd2 * 32 + lcol);
                bv[2 * nd2][0] = r[0]; bv[2 * nd2][1] = r[1];
                bv[2 * nd2 + 1][0] = r[2]; bv[2 * nd2 + 1][1] = r[3];
            }
            #pragma unroll
            for (int nd = 0; nd < 8; nd++)
                mma16816h(oacc[nd], ap, bv[nd]);
        }

        __syncthreads();
        if (c + 2 < 32) {
            const uint32_t nb = KV0 + (c & 1) * KVBUF;
            const size_t j0 = (size_t)((c + 2) * 64) * 3072;
            att_load(nb, k_b + j0, 2, t);
            att_load(nb + KTILEB, v_b + j0, 2, t);
            CP_COMMIT();
        }
    }

    // epilogue: normalize + fp16 write
    const float inv0 = 1.f / l0, inv1 = 1.f / l1;
    const int r0 = q0 + wid * 16 + (lane >> 2);
    #pragma unroll
    for (int nd = 0; nd < 8; nd++) {
        const int col = h * 64 + nd * 8 + (lane & 3) * 2;
        #pragma unroll
        for (int hrow = 0; hrow < 2; hrow++) {
            const float inv = hrow ? inv1 : inv0;
            const __half2 hv = __floats2half2_rn(oacc[nd][hrow * 2] * inv,
                                                 oacc[nd][hrow * 2 + 1] * inv);
            *(__half2*)(att + (rb + r0 + 8 * hrow) * 1024 + col) = hv;
        }
    }
}

// ------------------------- launch ------------------------------------------
extern "C" void kernel_launch(void* const* d_in, const int* in_sizes, int n_in,
                              void* d_out, int out_size)
{
    const float* x     = (const float*)d_in[0];
    const float* w_qkv = (const float*)d_in[1];
    const float* w_out = (const float*)d_in[2];
    const float* b_out = (const float*)d_in[3];
    float* out = (float*)d_out;

    __half *x16, *wq16, *wo16, *qkv16, *att16;
    cudaGetSymbolAddress((void**)&x16, g_x16);
    cudaGetSymbolAddress((void**)&wq16, g_wqkvt16);
    cudaGetSymbolAddress((void**)&wo16, g_woutt16);
    cudaGetSymbolAddress((void**)&qkv16, g_qkv16);
    cudaGetSymbolAddress((void**)&att16, g_att16);

    cudaFuncSetAttribute(gemm_f16<0>, cudaFuncAttributeMaxDynamicSharedMemorySize,
                         SMEM_G16_BYTES);
    cudaFuncSetAttribute(gemm_f16<1>, cudaFuncAttributeMaxDynamicSharedMemorySize,
                         SMEM_G16_BYTES);
    cudaFuncSetAttribute(attn_mma, cudaFuncAttributeMaxDynamicSharedMemorySize,
                         SMEM_ATT_BYTES);

    // prep
    convert_f16<<<(8192 * 1024 / 4 + 255) / 256, 256>>>(x, x16, 8192 * 1024 / 4);
    transpose_f16<<<dim3(3072 / 32, 1024 / 32), dim3(32, 8)>>>(
        w_qkv, wq16, 1024, 3072, 1024, ATT_SCALE * LOG2E);
    transpose_f16<<<dim3(1024 / 32, 1024 / 32), dim3(32, 8)>>>(
        w_out, wo16, 1024, 1024, 0, 1.f);

    // stage 1: qkv = x @ w_qkv (fp16)
    gemm_f16<0><<<dim3(3072 / 128, 8192 / 128), 256, SMEM_G16_BYTES>>>(
        x16, wq16, nullptr, qkv16, nullptr, 3072, 1024);

    // stage 2: flash attention (fp16), writes fp16 att
    attn_mma<<<dim3(2048 / 128, 64), 256, SMEM_ATT_BYTES>>>(qkv16, att16);

    // stage 3: out = att @ w_out + b (fp16, fp32 out)
    gemm_f16<1><<<dim3(1024 / 128, 8192 / 128), 256, SMEM_G16_BYTES>>>(
        att16, wo16, b_out, nullptr, out, 1024, 1024);
}

// round 11
// speedup vs baseline: 9.0307x; 1.0336x over previous
#include <cuda_runtime.h>
#include <cuda_bf16.h>
#include <cuda_fp16.h>
#include <cstdint>

// ---------------------------------------------------------------------------
// Attention_71485435675049 — Round 11
// R10 + 4-stage cp.async multistage (ONE __syncthreads per K-chunk) in both
// gemm_f16 and attn_mma. Numerics identical to R10 (rel_err 6.5e-4).
// ---------------------------------------------------------------------------

#define ATT_SCALE 0.125f
#define LOG2E 1.4426950408889634f

// ------------------------- scratch (no allocs allowed) ----------------------
__device__ __half g_x16[8192 * 1024];
__device__ __half g_wqkvt16[3072 * 1024];    // [N,K] transposed fp16
__device__ __half g_woutt16[1024 * 1024];    // [N,K] transposed fp16
__device__ __half g_qkv16[8192 * 3072];
__device__ __half g_att16[8192 * 1024];

// ------------------------- PTX helpers -------------------------------------
__device__ __forceinline__ uint32_t smem_u32(const void* p) {
    uint32_t a;
    asm("{ .reg .u64 t; cvta.to.shared.u64 t, %1; cvt.u32.u64 %0, t; }"
        : "=r"(a) : "l"(p));
    return a;
}

__device__ __forceinline__ void cp_async16(uint32_t dst, const void* src) {
    asm volatile("cp.async.cg.shared.global [%0], [%1], 16;\n"
                 :: "r"(dst), "l"(src));
}
#define CP_COMMIT() asm volatile("cp.async.commit_group;\n" ::: "memory")
#define CP_WAIT(n)  asm volatile("cp.async.wait_group %0;\n" :: "n"(n) : "memory")

__device__ __forceinline__ void ldm_x4(uint32_t r[4], uint32_t addr) {
    asm volatile("ldmatrix.sync.aligned.m8n8.x4.shared.b16 {%0,%1,%2,%3}, [%4];"
                 : "=r"(r[0]), "=r"(r[1]), "=r"(r[2]), "=r"(r[3]) : "r"(addr));
}
__device__ __forceinline__ void ldm_x4_t(uint32_t r[4], uint32_t addr) {
    asm volatile("ldmatrix.sync.aligned.m8n8.x4.trans.shared.b16 {%0,%1,%2,%3}, [%4];"
                 : "=r"(r[0]), "=r"(r[1]), "=r"(r[2]), "=r"(r[3]) : "r"(addr));
}

__device__ __forceinline__ void mma16816h(float c[4], const uint32_t a[4],
                                          const uint32_t b[2]) {
    asm volatile(
        "mma.sync.aligned.m16n8k16.row.col.f32.f16.f16.f32 "
        "{%0,%1,%2,%3}, {%4,%5,%6,%7}, {%8,%9}, {%0,%1,%2,%3};"
        : "+f"(c[0]), "+f"(c[1]), "+f"(c[2]), "+f"(c[3])
        : "r"(a[0]), "r"(a[1]), "r"(a[2]), "r"(a[3]), "r"(b[0]), "r"(b[1]));
}

__device__ __forceinline__ float ex2(float x) {
    float r; asm("ex2.approx.f32 %0, %1;" : "=f"(r) : "f"(x)); return r;
}
__device__ __forceinline__ uint32_t pack_f16x2(float lo, float hi) {
    uint32_t d;
    asm("cvt.rn.f16x2.f32 %0, %1, %2;" : "=r"(d) : "f"(hi), "f"(lo));
    return d;
}

// ------------------------- conversion kernels ------------------------------
__global__ void convert_f16(const float* __restrict__ src,
                            __half* __restrict__ dst, int n4) {
    int i = blockIdx.x * blockDim.x + threadIdx.x;
    if (i >= n4) return;
    float4 v = ((const float4*)src)[i];
    ((__half2*)dst)[i * 2 + 0] = __floats2half2_rn(v.x, v.y);
    ((__half2*)dst)[i * 2 + 1] = __floats2half2_rn(v.z, v.w);
}

// src[K,N] fp32 -> out[N,K] fp16; cols < scale_cols scaled by `scale`
__global__ void transpose_f16(const float* __restrict__ src,
                              __half* __restrict__ dst,
                              int K, int N, int scale_cols, float scale) {
    __shared__ float tile[32][33];
    const int n0 = blockIdx.x * 32, k0 = blockIdx.y * 32;
    const int tx = threadIdx.x, ty = threadIdx.y;
    #pragma unroll
    for (int j = 0; j < 4; j++) {
        int r = ty + j * 8;
        float v = src[(size_t)(k0 + r) * N + n0 + tx];
        if (n0 + tx < scale_cols) v *= scale;
        tile[r][tx] = v;
    }
    __syncthreads();
    #pragma unroll
    for (int j = 0; j < 4; j++) {
        int b = ty + j * 8;
        dst[(size_t)(n0 + b) * K + k0 + tx] = __float2half_rn(tile[tx][b]);
    }
}

// ------------------------- fp16 multistage GEMM -----------------------------
constexpr int ROWB = 80;
constexpr int TILEB = 128 * ROWB;
constexpr int BUF16 = 2 * TILEB;              // A + B per stage
constexpr int SMEM_G16_BYTES = 4 * BUF16;     // 4 stages = 81920

__device__ __forceinline__ void load_tile_p(uint32_t dst, const void* src0,
                                            int row0, int k0, int K, int t) {
    const char* sp = (const char*)src0 + ((size_t)row0 * K + k0) * 2;
    const size_t rs = (size_t)K * 2;
    #pragma unroll
    for (int i = 0; i < 2; i++) {
        int s = i * 256 + t;
        int row = s >> 2, seg = (s & 3) * 16;
        cp_async16(dst + row * ROWB + seg, sp + (size_t)row * rs + seg);
    }
}

// MODE 0: write fp16 C. MODE 1: write fp32 C + bias.
template <int MODE>
__global__ __launch_bounds__(256) void gemm_f16(
    const __half* __restrict__ A, const __half* __restrict__ B,
    const float* __restrict__ bias,
    __half* __restrict__ Ch, float* __restrict__ Cf, int N, int K)
{
    extern __shared__ char smem[];
    const uint32_t sb = smem_u32(smem);
    const int t = threadIdx.x, wid = t >> 5, lane = t & 31;
    const int warp_m = wid & 3, warp_n = wid >> 2;

    const int rowA = blockIdx.y * 128, rowB = blockIdx.x * 128;
    const int nch = K / 32;

    float acc[2][8][4];
    #pragma unroll
    for (int mt = 0; mt < 2; mt++)
        #pragma unroll
        for (int nt = 0; nt < 8; nt++)
            #pragma unroll
            for (int j = 0; j < 4; j++) acc[mt][nt][j] = 0.f;

    // prologue: fill stages 0..2
    #pragma unroll
    for (int c = 0; c < 3; c++) {
        uint32_t bb = sb + c * BUF16;
        load_tile_p(bb, A, rowA, c * 32, K, t);
        load_tile_p(bb + TILEB, B, rowB, c * 32, K, t);
        CP_COMMIT();
    }

    const int lrow = lane & 15;
    const uint32_t lcol = (lane >> 4) << 4;

    for (int c = 0; c < nch; c++) {
        CP_WAIT(2);                 // stage c's group complete
        __syncthreads();            // all warps done with stage c-1 (= buffer (c+3)&3)
        if (c + 3 < nch) {
            uint32_t nb = sb + ((c + 3) & 3) * BUF16;
            load_tile_p(nb, A, rowA, (c + 3) * 32, K, t);
            load_tile_p(nb + TILEB, B, rowB, (c + 3) * 32, K, t);
        }
        CP_COMMIT();                // unconditional: keeps group ledger aligned

        const uint32_t bb = sb + (c & 3) * BUF16;
        const uint32_t sA = bb, sB = bb + TILEB;

        #pragma unroll
        for (int kk = 0; kk < 2; kk++) {
            const uint32_t coff = kk * 32 + lcol;
            uint32_t a4[2][4];
            #pragma unroll
            for (int mt = 0; mt < 2; mt++)
                ldm_x4(a4[mt], sA + (warp_m * 32 + mt * 16 + lrow) * ROWB + coff);
            uint32_t b2[8][2];
            #pragma unroll
            for (int g = 0; g < 4; g++) {
                uint32_t r[4];
                ldm_x4(r, sB + (warp_n * 64 + g * 16 + lrow) * ROWB + coff);
                b2[2 * g][0] = r[0]; b2[2 * g][1] = r[2];
                b2[2 * g + 1][0] = r[1]; b2[2 * g + 1][1] = r[3];
            }
            #pragma unroll
            for (int mt = 0; mt < 2; mt++)
                #pragma unroll
                for (int nt = 0; nt < 8; nt++)
                    mma16816h(acc[mt][nt], a4[mt], b2[nt]);
        }
    }

    #pragma unroll
    for (int mt = 0; mt < 2; mt++) {
        const int r0 = blockIdx.y * 128 + warp_m * 32 + mt * 16 + (lane >> 2);
        #pragma unroll
        for (int nt = 0; nt < 8; nt++) {
            const int col = blockIdx.x * 128 + warp_n * 64 + nt * 8 + (lane & 3) * 2;
            if (MODE == 1) {
                const float2 b2 = *(const float2*)(bias + col);
                *(float2*)(Cf + (size_t)r0 * N + col) =
                    make_float2(acc[mt][nt][0] + b2.x, acc[mt][nt][1] + b2.y);
                *(float2*)(Cf + (size_t)(r0 + 8) * N + col) =
                    make_float2(acc[mt][nt][2] + b2.x, acc[mt][nt][3] + b2.y);
            } else {
                #pragma unroll
                for (int hrow = 0; hrow < 2; hrow++) {
                    const __half2 hv = __floats2half2_rn(acc[mt][nt][hrow * 2],
                                                         acc[mt][nt][hrow * 2 + 1]);
                    *(__half2*)(Ch + (size_t)(r0 + 8 * hrow) * N + col) = hv;
                }
            }
        }
    }
}

// ------------------------- fp16 multistage flash attention ------------------
constexpr int AROWB = 144;
constexpr int QTILEB = 128 * AROWB;
constexpr int KTILEB = 64 * AROWB;
constexpr int KVBUF = 2 * KTILEB;                    // K + V per stage
constexpr int SMEM_ATT_BYTES = QTILEB + 4 * KVBUF;   // 92160

__device__ __forceinline__ void att_load(uint32_t dst, const __half* src,
                                         int rows256, int t) {
    #pragma unroll
    for (int i = 0; i < 4; i++) {
        if (i >= rows256) break;
        int s = i * 256 + t;
        int r = s >> 3, seg = (s & 7) * 16;
        cp_async16(dst + r * AROWB + seg, (const char*)src + (size_t)r * 6144 + seg);
    }
}

__global__ __launch_bounds__(256) void attn_mma(
    const __half* __restrict__ qkv, __half* __restrict__ att)
{
    extern __shared__ char smem[];
    const uint32_t sb = smem_u32(smem);
    const int t = threadIdx.x, wid = t >> 5, lane = t & 31;
    const int bh_ = blockIdx.y, b = bh_ >> 4, h = bh_ & 15;
    const int q0 = blockIdx.x * 128;
    const size_t rb = (size_t)b * 2048;

    const uint32_t QT = sb;
    const uint32_t KV0 = sb + QTILEB;
    const __half* k_b = qkv + rb * 3072 + 1024 + h * 64;
    const __half* v_b = qkv + rb * 3072 + 2048 + h * 64;

    // Q joins stage-0's commit group; stages 0..2 prefilled
    att_load(QT, qkv + (rb + q0) * 3072 + h * 64, 4, t);
    #pragma unroll
    for (int c = 0; c < 3; c++) {
        const uint32_t kb = KV0 + c * KVBUF;
        att_load(kb, k_b + (size_t)(c * 64) * 3072, 2, t);
        att_load(kb + KTILEB, v_b + (size_t)(c * 64) * 3072, 2, t);
        CP_COMMIT();
    }

    float oacc[8][4];
    #pragma unroll
    for (int nd = 0; nd < 8; nd++)
        #pragma unroll
        for (int j = 0; j < 4; j++) oacc[nd][j] = 0.f;
    float m0 = -1e30f, m1 = -1e30f, l0 = 0.f, l1 = 0.f;

    const int lrow = lane & 15;
    const uint32_t lcol = (lane >> 4) << 4;

    for (int c = 0; c < 32; c++) {
        CP_WAIT(2);
        __syncthreads();
        if (c + 3 < 32) {
            const uint32_t nb = KV0 + ((c + 3) & 3) * KVBUF;
            const size_t j0 = (size_t)((c + 3) * 64) * 3072;
            att_load(nb, k_b + j0, 2, t);
            att_load(nb + KTILEB, v_b + j0, 2, t);
        }
        CP_COMMIT();

        const uint32_t kb = KV0 + (c & 3) * KVBUF;
        const uint32_t sK = kb, sV = kb + KTILEB;

        float sacc[8][4];
        #pragma unroll
        for (int nt = 0; nt < 8; nt++)
            #pragma unroll
            for (int j = 0; j < 4; j++) sacc[nt][j] = 0.f;

        #pragma unroll
        for (int kt = 0; kt < 4; kt++) {
            const uint32_t coff = kt * 32 + lcol;
            uint32_t q4[4];
            ldm_x4(q4, QT + (wid * 16 + lrow) * AROWB + coff);
            uint32_t bk[8][2];
            #pragma unroll
            for (int g = 0; g < 4; g++) {
                uint32_t r[4];
                ldm_x4(r, sK + (g * 16 + lrow) * AROWB + coff);
                bk[2 * g][0] = r[0]; bk[2 * g][1] = r[2];
                bk[2 * g + 1][0] = r[1]; bk[2 * g + 1][1] = r[3];
            }
            #pragma unroll
            for (int nt = 0; nt < 8; nt++)
                mma16816h(sacc[nt], q4, bk[nt]);
        }

        float tm0 = -1e30f, tm1 = -1e30f;
        #pragma unroll
        for (int nt = 0; nt < 8; nt++) {
            tm0 = fmaxf(tm0, fmaxf(sacc[nt][0], sacc[nt][1]));
            tm1 = fmaxf(tm1, fmaxf(sacc[nt][2], sacc[nt][3]));
        }
        tm0 = fmaxf(tm0, __shfl_xor_sync(0xffffffffu, tm0, 1));
        tm0 = fmaxf(tm0, __shfl_xor_sync(0xffffffffu, tm0, 2));
        tm1 = fmaxf(tm1, __shfl_xor_sync(0xffffffffu, tm1, 1));
        tm1 = fmaxf(tm1, __shfl_xor_sync(0xffffffffu, tm1, 2));
        const float nm0 = fmaxf(m0, tm0), nm1 = fmaxf(m1, tm1);
        const float cr0 = ex2(m0 - nm0), cr1 = ex2(m1 - nm1);
        m0 = nm0; m1 = nm1;
        l0 *= cr0; l1 *= cr1;
        #pragma unroll
        for (int nd = 0; nd < 8; nd++) {
            oacc[nd][0] *= cr0; oacc[nd][1] *= cr0;
            oacc[nd][2] *= cr1; oacc[nd][3] *= cr1;
        }
        float rs0 = 0.f, rs1 = 0.f;
        #pragma unroll
        for (int nt = 0; nt < 8; nt++) {
            float p0 = ex2(sacc[nt][0] - m0), p1 = ex2(sacc[nt][1] - m0);
            float p2 = ex2(sacc[nt][2] - m1), p3 = ex2(sacc[nt][3] - m1);
            sacc[nt][0] = p0; sacc[nt][1] = p1; sacc[nt][2] = p2; sacc[nt][3] = p3;
            rs0 += p0 + p1; rs1 += p2 + p3;
        }
        rs0 += __shfl_xor_sync(0xffffffffu, rs0, 1);
        rs0 += __shfl_xor_sync(0xffffffffu, rs0, 2);
        rs1 += __shfl_xor_sync(0xffffffffu, rs1, 1);
        rs1 += __shfl_xor_sync(0xffffffffu, rs1, 2);
        l0 += rs0; l1 += rs1;

        #pragma unroll
        for (int kt = 0; kt < 4; kt++) {
            uint32_t ap[4];
            #pragma unroll
            for (int half = 0; half < 2; half++) {
                const float* sp = sacc[2 * kt + half];
                ap[half * 2 + 0] = pack_f16x2(sp[0], sp[1]);
                ap[half * 2 + 1] = pack_f16x2(sp[2], sp[3]);
            }
            uint32_t bv[8][2];
            #pragma unroll
            for (int nd2 = 0; nd2 < 4; nd2++) {
                uint32_t r[4];
                ldm_x4_t(r, sV + (kt * 16 + lrow) * AROWB + nd2 * 32 + lcol);
                bv[2 * nd2][0] = r[0]; bv[2 * nd2][1] = r[1];
                bv[2 * nd2 + 1][0] = r[2]; bv[2 * nd2 + 1][1] = r[3];
            }
            #pragma unroll
            for (int nd = 0; nd < 8; nd++)
                mma16816h(oacc[nd], ap, bv[nd]);
        }
    }

    // epilogue: normalize + fp16 write
    const float inv0 = 1.f / l0, inv1 = 1.f / l1;
    const int r0 = q0 + wid * 16 + (lane >> 2);
    #pragma unroll
    for (int nd = 0; nd < 8; nd++) {
        const int col = h * 64 + nd * 8 + (lane & 3) * 2;
        #pragma unroll
        for (int hrow = 0; hrow < 2; hrow++) {
            const float inv = hrow ? inv1 : inv0;
            const __half2 hv = __floats2half2_rn(oacc[nd][hrow * 2] * inv,
                                                 oacc[nd][hrow * 2 + 1] * inv);
            *(__half2*)(att + (rb + r0 + 8 * hrow) * 1024 + col) = hv;
        }
    }
}

// ------------------------- launch ------------------------------------------
extern "C" void kernel_launch(void* const* d_in, const int* in_sizes, int n_in,
                              void* d_out, int out_size)
{
    const float* x     = (const float*)d_in[0];
    const float* w_qkv = (const float*)d_in[1];
    const float* w_out = (const float*)d_in[2];
    const float* b_out = (const float*)d_in[3];
    float* out = (float*)d_out;

    __half *x16, *wq16, *wo16, *qkv16, *att16;
    cudaGetSymbolAddress((void**)&x16, g_x16);
    cudaGetSymbolAddress((void**)&wq16, g_wqkvt16);
    cudaGetSymbolAddress((void**)&wo16, g_woutt16);
    cudaGetSymbolAddress((void**)&qkv16, g_qkv16);
    cudaGetSymbolAddress((void**)&att16, g_att16);

    cudaFuncSetAttribute(gemm_f16<0>, cudaFuncAttributeMaxDynamicSharedMemorySize,
                         SMEM_G16_BYTES);
    cudaFuncSetAttribute(gemm_f16<1>, cudaFuncAttributeMaxDynamicSharedMemorySize,
                         SMEM_G16_BYTES);
    cudaFuncSetAttribute(attn_mma, cudaFuncAttributeMaxDynamicSharedMemorySize,
                         SMEM_ATT_BYTES);

    // prep
    convert_f16<<<(8192 * 1024 / 4 + 255) / 256, 256>>>(x, x16, 8192 * 1024 / 4);
    transpose_f16<<<dim3(3072 / 32, 1024 / 32), dim3(32, 8)>>>(
        w_qkv, wq16, 1024, 3072, 1024, ATT_SCALE * LOG2E);
    transpose_f16<<<dim3(1024 / 32, 1024 / 32), dim3(32, 8)>>>(
        w_out, wo16, 1024, 1024, 0, 1.f);

    // stage 1: qkv = x @ w_qkv (fp16)
    gemm_f16<0><<<dim3(3072 / 128, 8192 / 128), 256, SMEM_G16_BYTES>>>(
        x16, wq16, nullptr, qkv16, nullptr, 3072, 1024);

    // stage 2: flash attention (fp16), writes fp16 att
    attn_mma<<<dim3(2048 / 128, 64), 256, SMEM_ATT_BYTES>>>(qkv16, att16);

    // stage 3: out = att @ w_out + b (fp16, fp32 out)
    gemm_f16<1><<<dim3(1024 / 128, 8192 / 128), 256, SMEM_G16_BYTES>>>(
        att16, wo16, b_out, nullptr, out, 1024, 1024);
}